// round 7
// baseline (speedup 1.0000x reference)
#include <cuda_runtime.h>
#include <math.h>

// Problem constants
#define BTT     16
#define NM      1024
#define NL      64
#define NKV     1088
#define DIMM    128
#define HEADS   8
#define INNER   2048
#define QSCALE  0.08838834764831845f   // 128^-0.5
#define KVHALF  544

// Static device scratch
static __device__ float  g_pp[2 * 4 * 8 * DIMM * DIMM];       // split-K prep partials (4MB)
static __device__ float  g_m [HEADS * DIMM * DIMM];           // M_h = scale*Wq_h@Wk_h^T
static __device__ float  g_n [HEADS * DIMM * DIMM];           // N_h = Wv_h@Wo_h
static __device__ float  g_po[2 * BTT * HEADS * NL * DIMM];   // un-normalized O halves
static __device__ float2 g_ml2[2 * BTT * HEADS * NL];         // (m, l) per half per row

// fp32 -> tf32 round-to-nearest
__device__ __forceinline__ float cf(float x){
    unsigned u; asm("cvt.rna.tf32.f32 %0, %1;" : "=r"(u) : "f"(x));
    return __uint_as_float(u);
}

__device__ __forceinline__ void mma8(float* d, const unsigned* a, const unsigned* b){
    asm volatile("mma.sync.aligned.m16n8k8.row.col.f32.tf32.tf32.f32 "
        "{%0,%1,%2,%3}, {%4,%5,%6,%7}, {%8,%9}, {%0,%1,%2,%3};"
        : "+f"(d[0]), "+f"(d[1]), "+f"(d[2]), "+f"(d[3])
        : "r"(a[0]), "r"(a[1]), "r"(a[2]), "r"(a[3]), "r"(b[0]), "r"(b[1]));
}

// row r of concat(tensor[bt], latents[bt])
__device__ __forceinline__ const float* row_ptr(
    const float* __restrict__ tensor, const float* __restrict__ latents, int bt, int r)
{
    return (r < NM) ? tensor  + ((size_t)bt * NM + r)        * DIMM
                    : latents + ((size_t)bt * NL + (r - NM)) * DIMM;
}

// ===========================================================================
// Flash building blocks: 256 threads (8 warps), warp tile 16x64.
// A resident in smem At[k][72] (tf32). B double-buffered: Bs base holds
// [2][32][136]; one __syncthreads per K-chunk.
// ===========================================================================
#define BSW 4352   // words per Bs buffer (32*136)

__device__ __forceinline__ void frag_compute(
    const float* __restrict__ At, const float* __restrict__ Bs,
    float acc[8][4], int wm, int wn, int grp, int qid, int kbase)
{
    #pragma unroll
    for (int kk = 0; kk < 32; kk += 8) {
        unsigned a[4], b[8][2];
        const int k0 = kbase + kk;
        a[0] = __float_as_uint(At[(k0+qid  )*72 + wm+grp  ]);
        a[1] = __float_as_uint(At[(k0+qid  )*72 + wm+grp+8]);
        a[2] = __float_as_uint(At[(k0+qid+4)*72 + wm+grp  ]);
        a[3] = __float_as_uint(At[(k0+qid+4)*72 + wm+grp+8]);
        #pragma unroll
        for (int j = 0; j < 8; j++) {
            b[j][0] = __float_as_uint(Bs[(kk+qid  )*136 + wn+8*j+grp]);
            b[j][1] = __float_as_uint(Bs[(kk+qid+4)*136 + wn+8*j+grp]);
        }
        #pragma unroll
        for (int j = 0; j < 8; j++) mma8(acc[j], a, b[j]);
    }
}

__device__ __forceinline__ void stage_nn(float* Bs, const float4* pre, int br, int bc){
    #pragma unroll
    for (int i = 0; i < 4; i++) {
        float4 v;
        v.x = cf(pre[i].x); v.y = cf(pre[i].y);
        v.z = cf(pre[i].z); v.w = cf(pre[i].w);
        *(float4*)&Bs[br*136 + bc + 4*i] = v;
    }
}

__device__ __forceinline__ void stage_tb(float* Bs, const float4* pre, int bn, int bk0){
    #pragma unroll
    for (int i = 0; i < 4; i++) {
        const int k = bk0 + 4*i;
        Bs[(k+0)*136 + bn] = cf(pre[i].x);
        Bs[(k+1)*136 + bn] = cf(pre[i].y);
        Bs[(k+2)*136 + bn] = cf(pre[i].z);
        Bs[(k+3)*136 + bn] = cf(pre[i].w);
    }
}

// NN with contiguous weight B[k][n] (ldb row stride), K multiple of 32
__device__ __forceinline__ void gemm_w(
    const float* __restrict__ At, const float* __restrict__ Bg, int ldb, int K,
    float acc[8][4], float* __restrict__ BsBase,
    int wm, int wn, int grp, int qid, int t)
{
    const int br = t >> 3, bc = (t & 7) * 16;
    const float* Bp = Bg + (size_t)br * ldb + bc;
    float4 pre[4];
    #pragma unroll
    for (int i = 0; i < 4; i++) pre[i] = *(const float4*)(Bp + 4*i);
    stage_nn(BsBase, pre, br, bc);
    const int nk = K / 32;
    for (int c = 0; c < nk; c++) {
        __syncthreads();
        if (c + 1 < nk) {
            const float* Bp2 = Bp + (size_t)(c + 1) * 32 * ldb;
            #pragma unroll
            for (int i = 0; i < 4; i++) pre[i] = *(const float4*)(Bp2 + 4*i);
        }
        frag_compute(At, BsBase + (c & 1) * BSW, acc, wm, wn, grp, qid, c * 32);
        if (c + 1 < nk) stage_nn(BsBase + ((c + 1) & 1) * BSW, pre, br, bc);
    }
}

// TRANSB over in-rows: B row = concat row (row0 + bn), K = 128 dims
__device__ __forceinline__ void gemm_tb_in(
    const float* __restrict__ At,
    const float* __restrict__ tensor, const float* __restrict__ latents,
    int bt, int row0, int validN, float acc[8][4], float* __restrict__ BsBase,
    int wm, int wn, int grp, int qid, int t)
{
    const int bn = t >> 1, bk0 = (t & 1) * 16;
    const bool v = bn < validN;
    const float* Bp = row_ptr(tensor, latents, bt, row0 + (v ? bn : 0)) + bk0;
    float4 pre[4];
    #pragma unroll
    for (int i = 0; i < 4; i++)
        pre[i] = v ? *(const float4*)(Bp + 4*i) : make_float4(0.f,0.f,0.f,0.f);
    stage_tb(BsBase, pre, bn, bk0);
    for (int c = 0; c < DIMM; c += 32) {
        __syncthreads();
        if (c + 32 < DIMM) {
            #pragma unroll
            for (int i = 0; i < 4; i++)
                pre[i] = v ? *(const float4*)(Bp + (c + 32) + 4*i)
                           : make_float4(0.f,0.f,0.f,0.f);
        }
        frag_compute(At, BsBase + ((c >> 5) & 1) * BSW, acc, wm, wn, grp, qid, c);
        if (c + 32 < DIMM) stage_tb(BsBase + (((c >> 5) + 1) & 1) * BSW, pre, bn, bk0);
    }
}

// NN over in-rows: B row = concat row (row0 + c + br), K = kv count (mult of 32)
__device__ __forceinline__ void gemm_nn_in(
    const float* __restrict__ At,
    const float* __restrict__ tensor, const float* __restrict__ latents,
    int bt, int row0, int K, float acc[8][4], float* __restrict__ BsBase,
    int wm, int wn, int grp, int qid, int t)
{
    const int br = t >> 3, bc = (t & 7) * 16;
    float4 pre[4];
    {
        const float* Bp = row_ptr(tensor, latents, bt, row0 + br) + bc;
        #pragma unroll
        for (int i = 0; i < 4; i++) pre[i] = *(const float4*)(Bp + 4*i);
    }
    stage_nn(BsBase, pre, br, bc);
    for (int c = 0; c < K; c += 32) {
        __syncthreads();
        if (c + 32 < K) {
            const float* Bp2 = row_ptr(tensor, latents, bt, row0 + c + 32 + br) + bc;
            #pragma unroll
            for (int i = 0; i < 4; i++) pre[i] = *(const float4*)(Bp2 + 4*i);
        }
        frag_compute(At, BsBase + ((c >> 5) & 1) * BSW, acc, wm, wn, grp, qid, c);
        if (c + 32 < K) stage_nn(BsBase + (((c >> 5) + 1) & 1) * BSW, pre, br, bc);
    }
}

// ===========================================================================
// k_flash: grid 256 = (bt,h,half). tf32 tensor cores (proven R5 numerics).
// smem words: QWt 9216 | SXt 9216 | Bs 2x4352 | stats 192  = 109312 bytes
// ===========================================================================
#define FLASH_WORDS (9216 + 9216 + 2*BSW + 192)
#define FLASH_SMEM  (FLASH_WORDS * 4)

__global__ void __launch_bounds__(256, 2) k_flash(
    const float* __restrict__ tensor, const float* __restrict__ latents)
{
    extern __shared__ float sm[];
    float* QWt   = sm;                    // [128][72]
    float* SXt   = sm + 9216;             // staging / S / P [128][72]
    float* Bs    = sm + 2*9216;           // [2][32][136]
    float* m_run = Bs + 2*BSW;            // [64]
    float* l_run = m_run + 64;
    float* rsc   = l_run + 64;

    const int zz = blockIdx.x;
    const int z = zz >> 1, half = zz & 1;
    const int bt = z >> 3, h = z & 7;
    const int kvbase = half * KVHALF;

    const int t = threadIdx.x, warp = t >> 5, lane = t & 31;
    const int grp = lane >> 2, qid = lane & 3;
    const int wm = (warp & 3) * 16, wn = (warp >> 2) * 64;

    if (t < 64) { m_run[t] = -INFINITY; l_run[t] = 0.f; }

    // stage latents[bt] (64x128) transposed -> SXt[k][r]
    {
        const int r = t >> 2, k0 = (t & 3) * 32;
        const float* Lp = latents + (size_t)bt * NL * DIMM + (size_t)r * DIMM + k0;
        #pragma unroll
        for (int i = 0; i < 8; i++) {
            float4 v = *(const float4*)(Lp + 4*i);
            const int k = k0 + 4*i;
            SXt[(k+0)*72 + r] = cf(v.x);
            SXt[(k+1)*72 + r] = cf(v.y);
            SXt[(k+2)*72 + r] = cf(v.z);
            SXt[(k+3)*72 + r] = cf(v.w);
        }
    }
    __syncthreads();

    // QW = lat @ M_h
    {
        float qacc[8][4];
        #pragma unroll
        for (int j = 0; j < 8; j++)
            #pragma unroll
            for (int i = 0; i < 4; i++) qacc[j][i] = 0.f;
        gemm_w(SXt, g_m + (size_t)h * DIMM * DIMM, DIMM, DIMM,
               qacc, Bs, wm, wn, grp, qid, t);
        #pragma unroll
        for (int j = 0; j < 8; j++) {
            const int c = wn + 8*j + 2*qid;
            QWt[(c  )*72 + wm+grp  ] = cf(qacc[j][0]);
            QWt[(c+1)*72 + wm+grp  ] = cf(qacc[j][1]);
            QWt[(c  )*72 + wm+grp+8] = cf(qacc[j][2]);
            QWt[(c+1)*72 + wm+grp+8] = cf(qacc[j][3]);
        }
    }
    __syncthreads();

    float O[8][4];
    #pragma unroll
    for (int j = 0; j < 8; j++)
        #pragma unroll
        for (int i = 0; i < 4; i++) O[j][i] = 0.f;

    for (int kv0 = 0; kv0 < KVHALF; kv0 += 128) {
        const int valid = (KVHALF - kv0 < 128) ? (KVHALF - kv0) : 128;  // 128 or 32

        // S block = QW @ in_blk^T -> SXt[kv][row]
        float sacc[8][4];
        #pragma unroll
        for (int j = 0; j < 8; j++)
            #pragma unroll
            for (int i = 0; i < 4; i++) sacc[j][i] = 0.f;
        gemm_tb_in(QWt, tensor, latents, bt, kvbase + kv0, valid,
                   sacc, Bs, wm, wn, grp, qid, t);
        #pragma unroll
        for (int j = 0; j < 8; j++) {
            const int c = wn + 8*j + 2*qid;
            if (c < valid) {
                SXt[(c  )*72 + wm+grp  ] = sacc[j][0];
                SXt[(c  )*72 + wm+grp+8] = sacc[j][2];
            }
            if (c + 1 < valid) {
                SXt[(c+1)*72 + wm+grp  ] = sacc[j][1];
                SXt[(c+1)*72 + wm+grp+8] = sacc[j][3];
            }
        }
        __syncthreads();

        // online softmax: 4 threads per row
        {
            const int row = t >> 2, part = t & 3;
            const float mo = m_run[row];
            float mx = mo;
            #pragma unroll 8
            for (int i = 0; i < 32; i++) {
                const int c = part * 32 + i;
                if (c < valid) mx = fmaxf(mx, SXt[c*72 + row]);
            }
            mx = fmaxf(mx, __shfl_xor_sync(0xffffffffu, mx, 1));
            mx = fmaxf(mx, __shfl_xor_sync(0xffffffffu, mx, 2));
            float s = 0.f;
            #pragma unroll 8
            for (int i = 0; i < 32; i++) {
                const int c = part * 32 + i;
                if (c < valid) {
                    const float e = __expf(SXt[c*72 + row] - mx);
                    SXt[c*72 + row] = cf(e);
                    s += e;
                }
            }
            s += __shfl_xor_sync(0xffffffffu, s, 1);
            s += __shfl_xor_sync(0xffffffffu, s, 2);
            if (part == 0) {
                const float scale = __expf(mo - mx);
                l_run[row] = l_run[row] * scale + s;
                m_run[row] = mx;
                rsc[row]   = scale;
            }
        }
        __syncthreads();

        // rescale O, then O += P @ in_blk
        {
            const float s0 = rsc[wm+grp], s1 = rsc[wm+grp+8];
            #pragma unroll
            for (int j = 0; j < 8; j++) {
                O[j][0] *= s0; O[j][1] *= s0;
                O[j][2] *= s1; O[j][3] *= s1;
            }
        }
        gemm_nn_in(SXt, tensor, latents, bt, kvbase + kv0, valid,
                   O, Bs, wm, wn, grp, qid, t);
        __syncthreads();
    }

    // store un-normalized O + (m,l)
    if (t < 64) g_ml2[(size_t)zz * NL + t] = make_float2(m_run[t], l_run[t]);
    float* P = g_po + (size_t)zz * NL * DIMM;
    #pragma unroll
    for (int j = 0; j < 8; j++) {
        const int c = wn + 8*j + 2*qid;
        *(float2*)&P[(size_t)(wm+grp  ) * DIMM + c] = make_float2(O[j][0], O[j][1]);
        *(float2*)&P[(size_t)(wm+grp+8) * DIMM + c] = make_float2(O[j][2], O[j][3]);
    }
}

// ===========================================================================
// fp32 64x64 cores (proven) for split-K weight precompute
// ===========================================================================
__device__ __forceinline__ void f32_nn_core(
    const float* __restrict__ A, const float* __restrict__ B, float* __restrict__ C,
    int lda, int ldb, int ldc, int K, float alpha, int m0, int n0)
{
    __shared__ float As[16][68];
    __shared__ float Bsb[16][68];
    const int t  = threadIdx.x;
    const int tx = t & 15, ty = t >> 4;
    const int am = t >> 2, ak = (t & 3) << 2;
    const int bk = t >> 4, bn = (t & 15) << 2;
    const float* Ap = A + (size_t)(m0 + am) * lda + ak;
    const float* Bp = B + (size_t)bk * ldb + n0 + bn;
    float acc[4][4] = {};
    for (int kb = 0; kb < K; kb += 16) {
        float4 a = *(const float4*)(Ap + kb);
        float4 b = *(const float4*)(Bp + (size_t)kb * ldb);
        As[ak+0][am] = a.x; As[ak+1][am] = a.y; As[ak+2][am] = a.z; As[ak+3][am] = a.w;
        *(float4*)&Bsb[bk][bn] = b;
        __syncthreads();
        #pragma unroll
        for (int k = 0; k < 16; ++k) {
            float4 av = *(const float4*)&As[k][ty << 2];
            float4 bv = *(const float4*)&Bsb[k][tx << 2];
            acc[0][0] += av.x*bv.x; acc[0][1] += av.x*bv.y; acc[0][2] += av.x*bv.z; acc[0][3] += av.x*bv.w;
            acc[1][0] += av.y*bv.x; acc[1][1] += av.y*bv.y; acc[1][2] += av.y*bv.z; acc[1][3] += av.y*bv.w;
            acc[2][0] += av.z*bv.x; acc[2][1] += av.z*bv.y; acc[2][2] += av.z*bv.z; acc[2][3] += av.z*bv.w;
            acc[3][0] += av.w*bv.x; acc[3][1] += av.w*bv.y; acc[3][2] += av.w*bv.z; acc[3][3] += av.w*bv.w;
        }
        __syncthreads();
    }
    #pragma unroll
    for (int i = 0; i < 4; ++i) {
        float4 r;
        r.x = acc[i][0]*alpha; r.y = acc[i][1]*alpha; r.z = acc[i][2]*alpha; r.w = acc[i][3]*alpha;
        *(float4*)&C[(size_t)(m0 + (ty << 2) + i) * ldc + n0 + (tx << 2)] = r;
    }
}

__device__ __forceinline__ void f32_nt_core(
    const float* __restrict__ A, const float* __restrict__ Bm, float* __restrict__ C,
    int lda, int ldb, int ldc, int K, float alpha, int m0, int n0)
{
    __shared__ float As[16][68];
    __shared__ float Bsb[16][68];
    const int t  = threadIdx.x;
    const int tx = t & 15, ty = t >> 4;
    const int am = t >> 2, ak = (t & 3) << 2;
    const int bn = t >> 2, bq = (t & 3) << 2;
    const float* Ap = A  + (size_t)(m0 + am) * lda + ak;
    const float* Bp = Bm + (size_t)(n0 + bn) * ldb + bq;
    float acc[4][4] = {};
    for (int kb = 0; kb < K; kb += 16) {
        float4 a = *(const float4*)(Ap + kb);
        float4 b = *(const float4*)(Bp + kb);
        As[ak+0][am] = a.x; As[ak+1][am] = a.y; As[ak+2][am] = a.z; As[ak+3][am] = a.w;
        Bsb[bq+0][bn] = b.x; Bsb[bq+1][bn] = b.y; Bsb[bq+2][bn] = b.z; Bsb[bq+3][bn] = b.w;
        __syncthreads();
        #pragma unroll
        for (int k = 0; k < 16; ++k) {
            float4 av = *(const float4*)&As[k][ty << 2];
            float4 bv = *(const float4*)&Bsb[k][tx << 2];
            acc[0][0] += av.x*bv.x; acc[0][1] += av.x*bv.y; acc[0][2] += av.x*bv.z; acc[0][3] += av.x*bv.w;
            acc[1][0] += av.y*bv.x; acc[1][1] += av.y*bv.y; acc[1][2] += av.y*bv.z; acc[1][3] += av.y*bv.w;
            acc[2][0] += av.z*bv.x; acc[2][1] += av.z*bv.y; acc[2][2] += av.z*bv.z; acc[2][3] += av.z*bv.w;
            acc[3][0] += av.w*bv.x; acc[3][1] += av.w*bv.y; acc[3][2] += av.w*bv.z; acc[3][3] += av.w*bv.w;
        }
        __syncthreads();
    }
    #pragma unroll
    for (int i = 0; i < 4; ++i) {
        float4 r;
        r.x = acc[i][0]*alpha; r.y = acc[i][1]*alpha; r.z = acc[i][2]*alpha; r.w = acc[i][3]*alpha;
        *(float4*)&C[(size_t)(m0 + (ty << 2) + i) * ldc + n0 + (tx << 2)] = r;
    }
}

// k_prep_part: grid 256 = {M:128, N:128}, each CTA 64x64 output tile, K=64 slice
__global__ void k_prep_part(const float* __restrict__ Wq, const float* __restrict__ Wkv,
                            const float* __restrict__ Wo)
{
    const int b = blockIdx.x;
    const int isN = b >> 7, idx = b & 127;
    const int h = idx >> 4, sub = (idx >> 2) & 3, ks = idx & 3;
    const int m0 = (sub >> 1) * 64, n0 = (sub & 1) * 64, k0 = ks * 64;
    float* C = g_pp + ((size_t)(isN * 4 + ks) * 8 + h) * (DIMM * DIMM);
    if (!isN)
        f32_nt_core(Wq + h * 256 + k0, Wkv + h * 256 + k0, C,
                    INNER, 2 * INNER, DIMM, 64, 1.0f, m0, n0);
    else
        f32_nn_core(Wkv + INNER + h * 256 + k0, Wo + ((size_t)h * 256 + k0) * DIMM, C,
                    2 * INNER, DIMM, DIMM, 64, 1.0f, m0, n0);
}

// k_prep_red: sum the 4 K-slices -> g_m (x QSCALE) / g_n
__global__ void k_prep_red()
{
    const int i = blockIdx.x * 256 + threadIdx.x;   // float4 idx, 65536 total
    const int isN = i >> 15, j = i & 32767;         // 32768 float4 per half
    const int h = j >> 12, e = j & 4095;
    const float4* pp = (const float4*)g_pp;
    float4 r = make_float4(0.f, 0.f, 0.f, 0.f);
    #pragma unroll
    for (int ks = 0; ks < 4; ks++) {
        float4 a = pp[((size_t)(isN * 4 + ks) * 8 + h) * 4096 + e];
        r.x += a.x; r.y += a.y; r.z += a.z; r.w += a.w;
    }
    if (!isN) {
        r.x *= QSCALE; r.y *= QSCALE; r.z *= QSCALE; r.w *= QSCALE;
        ((float4*)g_m)[(size_t)h * 4096 + e] = r;
    } else {
        ((float4*)g_n)[(size_t)h * 4096 + e] = r;
    }
}

// ===========================================================================
// k_final: per bt, out = sum_h (combined PI_h) @ N_h as one K=1024 tf32 GEMM.
// Flash-combine (merge two KV halves + 1/l) fused into the A loader.
// ===========================================================================
__global__ void __launch_bounds__(128) k_final(float* __restrict__ out)
{
    __shared__ float As[32][72];
    __shared__ float Bsb[32][136];
    const int bt = blockIdx.x;
    const int t    = threadIdx.x;
    const int warp = t >> 5, lane = t & 31;
    const int grp  = lane >> 2, qid = lane & 3;
    const int wm   = (warp & 1) * 32, wn = (warp >> 1) * 64;
    const int arow = t >> 1, ak0 = (t & 1) * 16;
    const int brow = t >> 2, bcol = (t & 3) * 32;

    float e0a[8], e1a[8];
    #pragma unroll
    for (int h = 0; h < 8; h++) {
        const int z = bt * HEADS + h;
        float2 ml0 = g_ml2[(size_t)(z*2  ) * NL + arow];
        float2 ml1 = g_ml2[(size_t)(z*2+1) * NL + arow];
        const float mm = fmaxf(ml0.x, ml1.x);
        const float a0 = __expf(ml0.x - mm), a1 = __expf(ml1.x - mm);
        const float il = 1.0f / (ml0.y * a0 + ml1.y * a1);
        e0a[h] = a0 * il; e1a[h] = a1 * il;
    }

    float acc[2][8][4];
    #pragma unroll
    for (int f = 0; f < 2; f++)
        #pragma unroll
        for (int j = 0; j < 8; j++)
            #pragma unroll
            for (int i = 0; i < 4; i++) acc[f][j][i] = 0.f;

    for (int c = 0; c < 32; c++) {
        const int h = c >> 2, dk = (c & 3) * 32;
        const int z = bt * HEADS + h;
        const float e0 = e0a[h], e1 = e1a[h];
        const float* O0 = g_po + (size_t)(z*2  ) * NL * DIMM + (size_t)arow * DIMM + dk + ak0;
        const float* O1 = g_po + (size_t)(z*2+1) * NL * DIMM + (size_t)arow * DIMM + dk + ak0;
        const float* Bp = g_n + (size_t)h * DIMM * DIMM + (size_t)(dk + brow) * DIMM + bcol;
        #pragma unroll
        for (int i = 0; i < 4; i++) {
            float4 a = *(const float4*)(O0 + 4*i);
            float4 b = *(const float4*)(O1 + 4*i);
            const int kc = ak0 + 4*i;
            As[kc+0][arow] = cf(e0*a.x + e1*b.x);
            As[kc+1][arow] = cf(e0*a.y + e1*b.y);
            As[kc+2][arow] = cf(e0*a.z + e1*b.z);
            As[kc+3][arow] = cf(e0*a.w + e1*b.w);
        }
        #pragma unroll
        for (int i = 0; i < 8; i++) {
            float4 v = *(const float4*)(Bp + 4*i);
            float4 w;
            w.x = cf(v.x); w.y = cf(v.y); w.z = cf(v.z); w.w = cf(v.w);
            *(float4*)&Bsb[brow][bcol + 4*i] = w;
        }
        __syncthreads();
        #pragma unroll
        for (int kk = 0; kk < 32; kk += 8) {
            unsigned a[2][4], b[8][2];
            #pragma unroll
            for (int f = 0; f < 2; f++) {
                a[f][0] = __float_as_uint(As[kk+qid  ][wm+16*f+grp  ]);
                a[f][1] = __float_as_uint(As[kk+qid  ][wm+16*f+grp+8]);
                a[f][2] = __float_as_uint(As[kk+qid+4][wm+16*f+grp  ]);
                a[f][3] = __float_as_uint(As[kk+qid+4][wm+16*f+grp+8]);
            }
            #pragma unroll
            for (int j = 0; j < 8; j++) {
                b[j][0] = __float_as_uint(Bsb[kk+qid  ][wn+8*j+grp]);
                b[j][1] = __float_as_uint(Bsb[kk+qid+4][wn+8*j+grp]);
            }
            #pragma unroll
            for (int f = 0; f < 2; f++)
                #pragma unroll
                for (int j = 0; j < 8; j++) mma8(acc[f][j], a[f], b[j]);
        }
        __syncthreads();
    }

    float* C = out + (size_t)bt * NL * DIMM;
    #pragma unroll
    for (int f = 0; f < 2; f++) {
        const int r0 = wm + 16*f + grp;
        #pragma unroll
        for (int j = 0; j < 8; j++) {
            const int col = wn + 8*j + 2*qid;
            *(float2*)&C[(size_t)r0 * DIMM + col] = make_float2(acc[f][j][0], acc[f][j][1]);
            *(float2*)&C[(size_t)(r0+8) * DIMM + col] = make_float2(acc[f][j][2], acc[f][j][3]);
        }
    }
}

// ---------------------------------------------------------------------------

extern "C" void kernel_launch(void* const* d_in, const int* in_sizes, int n_in,
                              void* d_out, int out_size)
{
    const float* tensor  = (const float*)d_in[0];
    const float* latents = (const float*)d_in[1];
    const float* Wq      = (const float*)d_in[2];
    const float* Wkv     = (const float*)d_in[3];
    const float* Wo      = (const float*)d_in[4];
    float*       out     = (float*)d_out;

    (void)in_sizes; (void)n_in; (void)out_size;

    cudaFuncSetAttribute(k_flash, cudaFuncAttributeMaxDynamicSharedMemorySize, FLASH_SMEM);

    k_prep_part<<<256, 256>>>(Wq, Wkv, Wo);
    k_prep_red <<<256, 256>>>();
    k_flash    <<<2 * BTT * HEADS, 256, FLASH_SMEM>>>(tensor, latents);
    k_final    <<<BTT, 128>>>(out);
}

// round 8
// speedup vs baseline: 1.4560x; 1.4560x over previous
#include <cuda_runtime.h>
#include <math.h>

// Problem constants
#define BTT     16
#define NM      1024
#define NL      64
#define NKV     1088
#define DIMM    128
#define HEADS   8
#define INNER   2048
#define QSCALE  0.08838834764831845f   // 128^-0.5
#define KVHALF  544

// Static device scratch
static __device__ float  g_pp[2 * 4 * 8 * DIMM * DIMM];       // split-K prep partials
static __device__ float  g_m [HEADS * DIMM * DIMM];           // M_h = scale*Wq_h@Wk_h^T
static __device__ float  g_n [HEADS * DIMM * DIMM];           // N_h = Wv_h@Wo_h
static __device__ float  g_po[2 * BTT * HEADS * NL * DIMM];   // un-normalized O halves
static __device__ float2 g_ml2[2 * BTT * HEADS * NL];         // (m, l) per half per row
static __device__ float  g_fp [BTT * HEADS * NL * DIMM];      // per-head partials of out

// fp32 -> tf32 round-to-nearest
__device__ __forceinline__ float cf(float x){
    unsigned u; asm("cvt.rna.tf32.f32 %0, %1;" : "=r"(u) : "f"(x));
    return __uint_as_float(u);
}

__device__ __forceinline__ void mma8(float* d, const unsigned* a, const unsigned* b){
    asm volatile("mma.sync.aligned.m16n8k8.row.col.f32.tf32.tf32.f32 "
        "{%0,%1,%2,%3}, {%4,%5,%6,%7}, {%8,%9}, {%0,%1,%2,%3};"
        : "+f"(d[0]), "+f"(d[1]), "+f"(d[2]), "+f"(d[3])
        : "r"(a[0]), "r"(a[1]), "r"(a[2]), "r"(a[3]), "r"(b[0]), "r"(b[1]));
}

// row r of concat(tensor[bt], latents[bt])
__device__ __forceinline__ const float* row_ptr(
    const float* __restrict__ tensor, const float* __restrict__ latents, int bt, int r)
{
    return (r < NM) ? tensor  + ((size_t)bt * NM + r)        * DIMM
                    : latents + ((size_t)bt * NL + (r - NM)) * DIMM;
}

// ===========================================================================
// Flash building blocks (R7, kept): 256 threads (8 warps), warp tile 16x64.
// A resident in smem At[k][72] (tf32). B double-buffered [2][32][136].
// ===========================================================================
#define BSW 4352   // words per Bs buffer (32*136)

__device__ __forceinline__ void frag_compute(
    const float* __restrict__ At, const float* __restrict__ Bs,
    float acc[8][4], int wm, int wn, int grp, int qid, int kbase)
{
    #pragma unroll
    for (int kk = 0; kk < 32; kk += 8) {
        unsigned a[4], b[8][2];
        const int k0 = kbase + kk;
        a[0] = __float_as_uint(At[(k0+qid  )*72 + wm+grp  ]);
        a[1] = __float_as_uint(At[(k0+qid  )*72 + wm+grp+8]);
        a[2] = __float_as_uint(At[(k0+qid+4)*72 + wm+grp  ]);
        a[3] = __float_as_uint(At[(k0+qid+4)*72 + wm+grp+8]);
        #pragma unroll
        for (int j = 0; j < 8; j++) {
            b[j][0] = __float_as_uint(Bs[(kk+qid  )*136 + wn+8*j+grp]);
            b[j][1] = __float_as_uint(Bs[(kk+qid+4)*136 + wn+8*j+grp]);
        }
        #pragma unroll
        for (int j = 0; j < 8; j++) mma8(acc[j], a, b[j]);
    }
}

__device__ __forceinline__ void stage_nn(float* Bs, const float4* pre, int br, int bc){
    #pragma unroll
    for (int i = 0; i < 4; i++) {
        float4 v;
        v.x = cf(pre[i].x); v.y = cf(pre[i].y);
        v.z = cf(pre[i].z); v.w = cf(pre[i].w);
        *(float4*)&Bs[br*136 + bc + 4*i] = v;
    }
}

__device__ __forceinline__ void stage_tb(float* Bs, const float4* pre, int bn, int bk0){
    #pragma unroll
    for (int i = 0; i < 4; i++) {
        const int k = bk0 + 4*i;
        Bs[(k+0)*136 + bn] = cf(pre[i].x);
        Bs[(k+1)*136 + bn] = cf(pre[i].y);
        Bs[(k+2)*136 + bn] = cf(pre[i].z);
        Bs[(k+3)*136 + bn] = cf(pre[i].w);
    }
}

__device__ __forceinline__ void gemm_w(
    const float* __restrict__ At, const float* __restrict__ Bg, int ldb, int K,
    float acc[8][4], float* __restrict__ BsBase,
    int wm, int wn, int grp, int qid, int t)
{
    const int br = t >> 3, bc = (t & 7) * 16;
    const float* Bp = Bg + (size_t)br * ldb + bc;
    float4 pre[4];
    #pragma unroll
    for (int i = 0; i < 4; i++) pre[i] = *(const float4*)(Bp + 4*i);
    stage_nn(BsBase, pre, br, bc);
    const int nk = K / 32;
    for (int c = 0; c < nk; c++) {
        __syncthreads();
        if (c + 1 < nk) {
            const float* Bp2 = Bp + (size_t)(c + 1) * 32 * ldb;
            #pragma unroll
            for (int i = 0; i < 4; i++) pre[i] = *(const float4*)(Bp2 + 4*i);
        }
        frag_compute(At, BsBase + (c & 1) * BSW, acc, wm, wn, grp, qid, c * 32);
        if (c + 1 < nk) stage_nn(BsBase + ((c + 1) & 1) * BSW, pre, br, bc);
    }
}

__device__ __forceinline__ void gemm_tb_in(
    const float* __restrict__ At,
    const float* __restrict__ tensor, const float* __restrict__ latents,
    int bt, int row0, int validN, float acc[8][4], float* __restrict__ BsBase,
    int wm, int wn, int grp, int qid, int t)
{
    const int bn = t >> 1, bk0 = (t & 1) * 16;
    const bool v = bn < validN;
    const float* Bp = row_ptr(tensor, latents, bt, row0 + (v ? bn : 0)) + bk0;
    float4 pre[4];
    #pragma unroll
    for (int i = 0; i < 4; i++)
        pre[i] = v ? *(const float4*)(Bp + 4*i) : make_float4(0.f,0.f,0.f,0.f);
    stage_tb(BsBase, pre, bn, bk0);
    for (int c = 0; c < DIMM; c += 32) {
        __syncthreads();
        if (c + 32 < DIMM) {
            #pragma unroll
            for (int i = 0; i < 4; i++)
                pre[i] = v ? *(const float4*)(Bp + (c + 32) + 4*i)
                           : make_float4(0.f,0.f,0.f,0.f);
        }
        frag_compute(At, BsBase + ((c >> 5) & 1) * BSW, acc, wm, wn, grp, qid, c);
        if (c + 32 < DIMM) stage_tb(BsBase + (((c >> 5) + 1) & 1) * BSW, pre, bn, bk0);
    }
}

__device__ __forceinline__ void gemm_nn_in(
    const float* __restrict__ At,
    const float* __restrict__ tensor, const float* __restrict__ latents,
    int bt, int row0, int K, float acc[8][4], float* __restrict__ BsBase,
    int wm, int wn, int grp, int qid, int t)
{
    const int br = t >> 3, bc = (t & 7) * 16;
    float4 pre[4];
    {
        const float* Bp = row_ptr(tensor, latents, bt, row0 + br) + bc;
        #pragma unroll
        for (int i = 0; i < 4; i++) pre[i] = *(const float4*)(Bp + 4*i);
    }
    stage_nn(BsBase, pre, br, bc);
    for (int c = 0; c < K; c += 32) {
        __syncthreads();
        if (c + 32 < K) {
            const float* Bp2 = row_ptr(tensor, latents, bt, row0 + c + 32 + br) + bc;
            #pragma unroll
            for (int i = 0; i < 4; i++) pre[i] = *(const float4*)(Bp2 + 4*i);
        }
        frag_compute(At, BsBase + ((c >> 5) & 1) * BSW, acc, wm, wn, grp, qid, c);
        if (c + 32 < K) stage_nn(BsBase + (((c >> 5) + 1) & 1) * BSW, pre, br, bc);
    }
}

// ===========================================================================
// k_flash (R7, kept): grid 256 = (bt,h,half), tf32, double-buffered B.
// ===========================================================================
#define FLASH_WORDS (9216 + 9216 + 2*BSW + 192)
#define FLASH_SMEM  (FLASH_WORDS * 4)

__global__ void __launch_bounds__(256, 2) k_flash(
    const float* __restrict__ tensor, const float* __restrict__ latents)
{
    extern __shared__ float sm[];
    float* QWt   = sm;                    // [128][72]
    float* SXt   = sm + 9216;             // staging / S / P [128][72]
    float* Bs    = sm + 2*9216;           // [2][32][136]
    float* m_run = Bs + 2*BSW;            // [64]
    float* l_run = m_run + 64;
    float* rsc   = l_run + 64;

    const int zz = blockIdx.x;
    const int z = zz >> 1, half = zz & 1;
    const int bt = z >> 3, h = z & 7;
    const int kvbase = half * KVHALF;

    const int t = threadIdx.x, warp = t >> 5, lane = t & 31;
    const int grp = lane >> 2, qid = lane & 3;
    const int wm = (warp & 3) * 16, wn = (warp >> 2) * 64;

    if (t < 64) { m_run[t] = -INFINITY; l_run[t] = 0.f; }

    // stage latents[bt] (64x128) transposed -> SXt[k][r]
    {
        const int r = t >> 2, k0 = (t & 3) * 32;
        const float* Lp = latents + (size_t)bt * NL * DIMM + (size_t)r * DIMM + k0;
        #pragma unroll
        for (int i = 0; i < 8; i++) {
            float4 v = *(const float4*)(Lp + 4*i);
            const int k = k0 + 4*i;
            SXt[(k+0)*72 + r] = cf(v.x);
            SXt[(k+1)*72 + r] = cf(v.y);
            SXt[(k+2)*72 + r] = cf(v.z);
            SXt[(k+3)*72 + r] = cf(v.w);
        }
    }
    __syncthreads();

    // QW = lat @ M_h
    {
        float qacc[8][4];
        #pragma unroll
        for (int j = 0; j < 8; j++)
            #pragma unroll
            for (int i = 0; i < 4; i++) qacc[j][i] = 0.f;
        gemm_w(SXt, g_m + (size_t)h * DIMM * DIMM, DIMM, DIMM,
               qacc, Bs, wm, wn, grp, qid, t);
        #pragma unroll
        for (int j = 0; j < 8; j++) {
            const int c = wn + 8*j + 2*qid;
            QWt[(c  )*72 + wm+grp  ] = cf(qacc[j][0]);
            QWt[(c+1)*72 + wm+grp  ] = cf(qacc[j][1]);
            QWt[(c  )*72 + wm+grp+8] = cf(qacc[j][2]);
            QWt[(c+1)*72 + wm+grp+8] = cf(qacc[j][3]);
        }
    }
    __syncthreads();

    float O[8][4];
    #pragma unroll
    for (int j = 0; j < 8; j++)
        #pragma unroll
        for (int i = 0; i < 4; i++) O[j][i] = 0.f;

    for (int kv0 = 0; kv0 < KVHALF; kv0 += 128) {
        const int valid = (KVHALF - kv0 < 128) ? (KVHALF - kv0) : 128;  // 128 or 32

        float sacc[8][4];
        #pragma unroll
        for (int j = 0; j < 8; j++)
            #pragma unroll
            for (int i = 0; i < 4; i++) sacc[j][i] = 0.f;
        gemm_tb_in(QWt, tensor, latents, bt, kvbase + kv0, valid,
                   sacc, Bs, wm, wn, grp, qid, t);
        #pragma unroll
        for (int j = 0; j < 8; j++) {
            const int c = wn + 8*j + 2*qid;
            if (c < valid) {
                SXt[(c  )*72 + wm+grp  ] = sacc[j][0];
                SXt[(c  )*72 + wm+grp+8] = sacc[j][2];
            }
            if (c + 1 < valid) {
                SXt[(c+1)*72 + wm+grp  ] = sacc[j][1];
                SXt[(c+1)*72 + wm+grp+8] = sacc[j][3];
            }
        }
        __syncthreads();

        {
            const int row = t >> 2, part = t & 3;
            const float mo = m_run[row];
            float mx = mo;
            #pragma unroll 8
            for (int i = 0; i < 32; i++) {
                const int c = part * 32 + i;
                if (c < valid) mx = fmaxf(mx, SXt[c*72 + row]);
            }
            mx = fmaxf(mx, __shfl_xor_sync(0xffffffffu, mx, 1));
            mx = fmaxf(mx, __shfl_xor_sync(0xffffffffu, mx, 2));
            float s = 0.f;
            #pragma unroll 8
            for (int i = 0; i < 32; i++) {
                const int c = part * 32 + i;
                if (c < valid) {
                    const float e = __expf(SXt[c*72 + row] - mx);
                    SXt[c*72 + row] = cf(e);
                    s += e;
                }
            }
            s += __shfl_xor_sync(0xffffffffu, s, 1);
            s += __shfl_xor_sync(0xffffffffu, s, 2);
            if (part == 0) {
                const float scale = __expf(mo - mx);
                l_run[row] = l_run[row] * scale + s;
                m_run[row] = mx;
                rsc[row]   = scale;
            }
        }
        __syncthreads();

        {
            const float s0 = rsc[wm+grp], s1 = rsc[wm+grp+8];
            #pragma unroll
            for (int j = 0; j < 8; j++) {
                O[j][0] *= s0; O[j][1] *= s0;
                O[j][2] *= s1; O[j][3] *= s1;
            }
        }
        gemm_nn_in(SXt, tensor, latents, bt, kvbase + kv0, valid,
                   O, Bs, wm, wn, grp, qid, t);
        __syncthreads();
    }

    if (t < 64) g_ml2[(size_t)zz * NL + t] = make_float2(m_run[t], l_run[t]);
    float* P = g_po + (size_t)zz * NL * DIMM;
    #pragma unroll
    for (int j = 0; j < 8; j++) {
        const int c = wn + 8*j + 2*qid;
        *(float2*)&P[(size_t)(wm+grp  ) * DIMM + c] = make_float2(O[j][0], O[j][1]);
        *(float2*)&P[(size_t)(wm+grp+8) * DIMM + c] = make_float2(O[j][2], O[j][3]);
    }
}

// ===========================================================================
// fp32 64x64 cores for split-K weight precompute (R7, kept)
// ===========================================================================
__device__ __forceinline__ void f32_nn_core(
    const float* __restrict__ A, const float* __restrict__ B, float* __restrict__ C,
    int lda, int ldb, int ldc, int K, float alpha, int m0, int n0)
{
    __shared__ float As[16][68];
    __shared__ float Bsb[16][68];
    const int t  = threadIdx.x;
    const int tx = t & 15, ty = t >> 4;
    const int am = t >> 2, ak = (t & 3) << 2;
    const int bk = t >> 4, bn = (t & 15) << 2;
    const float* Ap = A + (size_t)(m0 + am) * lda + ak;
    const float* Bp = B + (size_t)bk * ldb + n0 + bn;
    float acc[4][4] = {};
    for (int kb = 0; kb < K; kb += 16) {
        float4 a = *(const float4*)(Ap + kb);
        float4 b = *(const float4*)(Bp + (size_t)kb * ldb);
        As[ak+0][am] = a.x; As[ak+1][am] = a.y; As[ak+2][am] = a.z; As[ak+3][am] = a.w;
        *(float4*)&Bsb[bk][bn] = b;
        __syncthreads();
        #pragma unroll
        for (int k = 0; k < 16; ++k) {
            float4 av = *(const float4*)&As[k][ty << 2];
            float4 bv = *(const float4*)&Bsb[k][tx << 2];
            acc[0][0] += av.x*bv.x; acc[0][1] += av.x*bv.y; acc[0][2] += av.x*bv.z; acc[0][3] += av.x*bv.w;
            acc[1][0] += av.y*bv.x; acc[1][1] += av.y*bv.y; acc[1][2] += av.y*bv.z; acc[1][3] += av.y*bv.w;
            acc[2][0] += av.z*bv.x; acc[2][1] += av.z*bv.y; acc[2][2] += av.z*bv.z; acc[2][3] += av.z*bv.w;
            acc[3][0] += av.w*bv.x; acc[3][1] += av.w*bv.y; acc[3][2] += av.w*bv.z; acc[3][3] += av.w*bv.w;
        }
        __syncthreads();
    }
    #pragma unroll
    for (int i = 0; i < 4; ++i) {
        float4 r;
        r.x = acc[i][0]*alpha; r.y = acc[i][1]*alpha; r.z = acc[i][2]*alpha; r.w = acc[i][3]*alpha;
        *(float4*)&C[(size_t)(m0 + (ty << 2) + i) * ldc + n0 + (tx << 2)] = r;
    }
}

__device__ __forceinline__ void f32_nt_core(
    const float* __restrict__ A, const float* __restrict__ Bm, float* __restrict__ C,
    int lda, int ldb, int ldc, int K, float alpha, int m0, int n0)
{
    __shared__ float As[16][68];
    __shared__ float Bsb[16][68];
    const int t  = threadIdx.x;
    const int tx = t & 15, ty = t >> 4;
    const int am = t >> 2, ak = (t & 3) << 2;
    const int bn = t >> 2, bq = (t & 3) << 2;
    const float* Ap = A  + (size_t)(m0 + am) * lda + ak;
    const float* Bp = Bm + (size_t)(n0 + bn) * ldb + bq;
    float acc[4][4] = {};
    for (int kb = 0; kb < K; kb += 16) {
        float4 a = *(const float4*)(Ap + kb);
        float4 b = *(const float4*)(Bp + kb);
        As[ak+0][am] = a.x; As[ak+1][am] = a.y; As[ak+2][am] = a.z; As[ak+3][am] = a.w;
        Bsb[bq+0][bn] = b.x; Bsb[bq+1][bn] = b.y; Bsb[bq+2][bn] = b.z; Bsb[bq+3][bn] = b.w;
        __syncthreads();
        #pragma unroll
        for (int k = 0; k < 16; ++k) {
            float4 av = *(const float4*)&As[k][ty << 2];
            float4 bv = *(const float4*)&Bsb[k][tx << 2];
            acc[0][0] += av.x*bv.x; acc[0][1] += av.x*bv.y; acc[0][2] += av.x*bv.z; acc[0][3] += av.x*bv.w;
            acc[1][0] += av.y*bv.x; acc[1][1] += av.y*bv.y; acc[1][2] += av.y*bv.z; acc[1][3] += av.y*bv.w;
            acc[2][0] += av.z*bv.x; acc[2][1] += av.z*bv.y; acc[2][2] += av.z*bv.z; acc[2][3] += av.z*bv.w;
            acc[3][0] += av.w*bv.x; acc[3][1] += av.w*bv.y; acc[3][2] += av.w*bv.z; acc[3][3] += av.w*bv.w;
        }
        __syncthreads();
    }
    #pragma unroll
    for (int i = 0; i < 4; ++i) {
        float4 r;
        r.x = acc[i][0]*alpha; r.y = acc[i][1]*alpha; r.z = acc[i][2]*alpha; r.w = acc[i][3]*alpha;
        *(float4*)&C[(size_t)(m0 + (ty << 2) + i) * ldc + n0 + (tx << 2)] = r;
    }
}

__global__ void k_prep_part(const float* __restrict__ Wq, const float* __restrict__ Wkv,
                            const float* __restrict__ Wo)
{
    const int b = blockIdx.x;
    const int isN = b >> 7, idx = b & 127;
    const int h = idx >> 4, sub = (idx >> 2) & 3, ks = idx & 3;
    const int m0 = (sub >> 1) * 64, n0 = (sub & 1) * 64, k0 = ks * 64;
    float* C = g_pp + ((size_t)(isN * 4 + ks) * 8 + h) * (DIMM * DIMM);
    if (!isN)
        f32_nt_core(Wq + h * 256 + k0, Wkv + h * 256 + k0, C,
                    INNER, 2 * INNER, DIMM, 64, 1.0f, m0, n0);
    else
        f32_nn_core(Wkv + INNER + h * 256 + k0, Wo + ((size_t)h * 256 + k0) * DIMM, C,
                    2 * INNER, DIMM, DIMM, 64, 1.0f, m0, n0);
}

__global__ void k_prep_red()
{
    const int i = blockIdx.x * 256 + threadIdx.x;   // float4 idx, 65536 total
    const int isN = i >> 15, j = i & 32767;
    const int h = j >> 12, e = j & 4095;
    const float4* pp = (const float4*)g_pp;
    float4 r = make_float4(0.f, 0.f, 0.f, 0.f);
    #pragma unroll
    for (int ks = 0; ks < 4; ks++) {
        float4 a = pp[((size_t)(isN * 4 + ks) * 8 + h) * 4096 + e];
        r.x += a.x; r.y += a.y; r.z += a.z; r.w += a.w;
    }
    if (!isN) {
        r.x *= QSCALE; r.y *= QSCALE; r.z *= QSCALE; r.w *= QSCALE;
        ((float4*)g_m)[(size_t)h * 4096 + e] = r;
    } else {
        ((float4*)g_n)[(size_t)h * 4096 + e] = r;
    }
}

// ===========================================================================
// k_final_part (R5, proven 10.6us): per (h, bt) partial_h = PI_h @ N_h with
// flash-combine fused into the A loader. 128 threads, grid (8, 16).
// ===========================================================================
__global__ void __launch_bounds__(128) k_final_part()
{
    __shared__ float As[32][72];
    __shared__ float Bsb[32][136];
    const int h = blockIdx.x, bt = blockIdx.y;
    const int z = bt * HEADS + h;
    const float* B = g_n + (size_t)h * DIMM * DIMM;
    float*       C = g_fp + (size_t)z * NL * DIMM;

    const int t    = threadIdx.x;
    const int warp = t >> 5, lane = t & 31;
    const int grp  = lane >> 2, qid = lane & 3;
    const int wm   = (warp & 1) * 32, wn = (warp >> 1) * 64;

    const int arow = t >> 1, ak0 = (t & 1) * 16;

    float2 ml0 = g_ml2[(size_t)(z*2  ) * NL + arow];
    float2 ml1 = g_ml2[(size_t)(z*2+1) * NL + arow];
    const float mm = fmaxf(ml0.x, ml1.x);
    const float a0 = __expf(ml0.x - mm), a1 = __expf(ml1.x - mm);
    const float il = 1.0f / (ml0.y * a0 + ml1.y * a1);
    const float e0 = a0 * il, e1 = a1 * il;

    const float* O0 = g_po + (size_t)(z*2  ) * NL * DIMM + (size_t)arow * DIMM + ak0;
    const float* O1 = g_po + (size_t)(z*2+1) * NL * DIMM + (size_t)arow * DIMM + ak0;
    const int brow = t >> 2, bcol = (t & 3) * 32;
    const float* Bp = B + (size_t)brow * DIMM + bcol;

    float acc[2][8][4];
    #pragma unroll
    for (int f = 0; f < 2; f++)
        #pragma unroll
        for (int j = 0; j < 8; j++)
            #pragma unroll
            for (int i = 0; i < 4; i++) acc[f][j][i] = 0.f;

    float4 o0[4], o1[4], br[8];
    #pragma unroll
    for (int i = 0; i < 4; i++) {
        o0[i] = *(const float4*)(O0 + 4*i);
        o1[i] = *(const float4*)(O1 + 4*i);
    }
    #pragma unroll
    for (int i = 0; i < 8; i++) br[i] = *(const float4*)(Bp + 4*i);

    const int nk = DIMM / 32;   // 4
    for (int c = 0; c < nk; c++) {
        #pragma unroll
        for (int i = 0; i < 4; i++) {
            const int kc = ak0 + 4*i;
            As[kc+0][arow] = cf(e0*o0[i].x + e1*o1[i].x);
            As[kc+1][arow] = cf(e0*o0[i].y + e1*o1[i].y);
            As[kc+2][arow] = cf(e0*o0[i].z + e1*o1[i].z);
            As[kc+3][arow] = cf(e0*o0[i].w + e1*o1[i].w);
        }
        #pragma unroll
        for (int i = 0; i < 8; i++) {
            float4 v;
            v.x = cf(br[i].x); v.y = cf(br[i].y);
            v.z = cf(br[i].z); v.w = cf(br[i].w);
            *(float4*)&Bsb[brow][bcol + 4*i] = v;
        }
        __syncthreads();
        if (c + 1 < nk) {
            #pragma unroll
            for (int i = 0; i < 4; i++) {
                o0[i] = *(const float4*)(O0 + (c+1)*32 + 4*i);
                o1[i] = *(const float4*)(O1 + (c+1)*32 + 4*i);
            }
            const float* Bp2 = Bp + (size_t)(c + 1) * 32 * DIMM;
            #pragma unroll
            for (int i = 0; i < 8; i++) br[i] = *(const float4*)(Bp2 + 4*i);
        }
        #pragma unroll
        for (int kk = 0; kk < 32; kk += 8) {
            unsigned a[2][4], b[8][2];
            #pragma unroll
            for (int f = 0; f < 2; f++) {
                a[f][0] = __float_as_uint(As[kk+qid  ][wm+16*f+grp  ]);
                a[f][1] = __float_as_uint(As[kk+qid  ][wm+16*f+grp+8]);
                a[f][2] = __float_as_uint(As[kk+qid+4][wm+16*f+grp  ]);
                a[f][3] = __float_as_uint(As[kk+qid+4][wm+16*f+grp+8]);
            }
            #pragma unroll
            for (int j = 0; j < 8; j++) {
                b[j][0] = __float_as_uint(Bsb[kk+qid  ][wn+8*j+grp]);
                b[j][1] = __float_as_uint(Bsb[kk+qid+4][wn+8*j+grp]);
            }
            #pragma unroll
            for (int f = 0; f < 2; f++)
                #pragma unroll
                for (int j = 0; j < 8; j++) mma8(acc[f][j], a[f], b[j]);
        }
        __syncthreads();
    }
    #pragma unroll
    for (int f = 0; f < 2; f++) {
        const int r0 = wm + 16*f + grp;
        #pragma unroll
        for (int j = 0; j < 8; j++) {
            const int col = wn + 8*j + 2*qid;
            *(float2*)&C[(size_t)r0 * DIMM + col] = make_float2(acc[f][j][0], acc[f][j][1]);
            *(float2*)&C[(size_t)(r0+8) * DIMM + col] = make_float2(acc[f][j][2], acc[f][j][3]);
        }
    }
}

// reduce 8 per-head partials -> out
__global__ void k_final_red(float* __restrict__ out)
{
    const int i = blockIdx.x * 256 + threadIdx.x;   // float4 index, 32768 total
    const int bt = i >> 11, inner = i & 2047;
    const float4* fp = (const float4*)g_fp;
    float4 r = make_float4(0.f, 0.f, 0.f, 0.f);
    #pragma unroll
    for (int h = 0; h < 8; h++) {
        float4 a = fp[((size_t)bt * 8 + h) * 2048 + inner];
        r.x += a.x; r.y += a.y; r.z += a.z; r.w += a.w;
    }
    ((float4*)out)[i] = r;
}

// ---------------------------------------------------------------------------

extern "C" void kernel_launch(void* const* d_in, const int* in_sizes, int n_in,
                              void* d_out, int out_size)
{
    const float* tensor  = (const float*)d_in[0];
    const float* latents = (const float*)d_in[1];
    const float* Wq      = (const float*)d_in[2];
    const float* Wkv     = (const float*)d_in[3];
    const float* Wo      = (const float*)d_in[4];
    float*       out     = (float*)d_out;

    (void)in_sizes; (void)n_in; (void)out_size;

    cudaFuncSetAttribute(k_flash, cudaFuncAttributeMaxDynamicSharedMemorySize, FLASH_SMEM);

    k_prep_part <<<256, 256>>>(Wq, Wkv, Wo);
    k_prep_red  <<<256, 256>>>();
    k_flash     <<<2 * BTT * HEADS, 256, FLASH_SMEM>>>(tensor, latents);
    k_final_part<<<dim3(HEADS, BTT), 128>>>();
    k_final_red <<<(BTT * NL * DIMM / 4) / 256, 256>>>(out);
}

// round 9
// speedup vs baseline: 1.5855x; 1.0890x over previous
#include <cuda_runtime.h>
#include <math.h>

// Problem constants
#define BTT     16
#define NM      1024
#define NL      64
#define NKV     1088
#define DIMM    128
#define HEADS   8
#define INNER   2048
#define QSCALE  0.08838834764831845f   // 128^-0.5
#define KVHALF  544

// Static device scratch
static __device__ float  g_pp[2 * 4 * 8 * DIMM * DIMM];       // split-K prep partials
static __device__ float  g_m [HEADS * DIMM * DIMM];           // M_h = scale*Wq_h@Wk_h^T
static __device__ float  g_n [HEADS * DIMM * DIMM];           // N_h = Wv_h@Wo_h
static __device__ float  g_po[2 * BTT * HEADS * NL * DIMM];   // un-normalized O halves
static __device__ float2 g_ml2[2 * BTT * HEADS * NL];         // (m, l) per half per row
static __device__ float  g_fp [BTT * HEADS * NL * DIMM];      // per-head partials of out

// fp32 -> tf32 round-to-nearest
__device__ __forceinline__ float cf(float x){
    unsigned u; asm("cvt.rna.tf32.f32 %0, %1;" : "=r"(u) : "f"(x));
    return __uint_as_float(u);
}

__device__ __forceinline__ void mma8(float* d, const unsigned* a, const unsigned* b){
    asm volatile("mma.sync.aligned.m16n8k8.row.col.f32.tf32.tf32.f32 "
        "{%0,%1,%2,%3}, {%4,%5,%6,%7}, {%8,%9}, {%0,%1,%2,%3};"
        : "+f"(d[0]), "+f"(d[1]), "+f"(d[2]), "+f"(d[3])
        : "r"(a[0]), "r"(a[1]), "r"(a[2]), "r"(a[3]), "r"(b[0]), "r"(b[1]));
}

// row r of concat(tensor[bt], latents[bt])
__device__ __forceinline__ const float* row_ptr(
    const float* __restrict__ tensor, const float* __restrict__ latents, int bt, int r)
{
    return (r < NM) ? tensor  + ((size_t)bt * NM + r)        * DIMM
                    : latents + ((size_t)bt * NL + (r - NM)) * DIMM;
}

// ===========================================================================
// Flash building blocks: 256 threads (8 warps).
// A resident in smem At[k][72] (tf32). B double-buffered [2][32][136].
// ===========================================================================
#define BSW 4352   // words per Bs buffer (32*136)

// full-width fragment compute: warp tile 16x64 (acc[8][4])
__device__ __forceinline__ void frag_compute(
    const float* __restrict__ At, const float* __restrict__ Bs,
    float acc[8][4], int wm, int wn, int grp, int qid, int kbase)
{
    #pragma unroll
    for (int kk = 0; kk < 32; kk += 8) {
        unsigned a[4], b[8][2];
        const int k0 = kbase + kk;
        a[0] = __float_as_uint(At[(k0+qid  )*72 + wm+grp  ]);
        a[1] = __float_as_uint(At[(k0+qid  )*72 + wm+grp+8]);
        a[2] = __float_as_uint(At[(k0+qid+4)*72 + wm+grp  ]);
        a[3] = __float_as_uint(At[(k0+qid+4)*72 + wm+grp+8]);
        #pragma unroll
        for (int j = 0; j < 8; j++) {
            b[j][0] = __float_as_uint(Bs[(kk+qid  )*136 + wn+8*j+grp]);
            b[j][1] = __float_as_uint(Bs[(kk+qid+4)*136 + wn+8*j+grp]);
        }
        #pragma unroll
        for (int j = 0; j < 8; j++) mma8(acc[j], a, b[j]);
    }
}

// half-width fragment compute: warp tile 16x32 (acc[4][4]) — lower reg pressure
__device__ __forceinline__ void frag_compute_h(
    const float* __restrict__ At, const float* __restrict__ Bs,
    float acc[4][4], int wm, int wn2, int grp, int qid, int kbase)
{
    #pragma unroll
    for (int kk = 0; kk < 32; kk += 8) {
        unsigned a[4], b[4][2];
        const int k0 = kbase + kk;
        a[0] = __float_as_uint(At[(k0+qid  )*72 + wm+grp  ]);
        a[1] = __float_as_uint(At[(k0+qid  )*72 + wm+grp+8]);
        a[2] = __float_as_uint(At[(k0+qid+4)*72 + wm+grp  ]);
        a[3] = __float_as_uint(At[(k0+qid+4)*72 + wm+grp+8]);
        #pragma unroll
        for (int j = 0; j < 4; j++) {
            b[j][0] = __float_as_uint(Bs[(kk+qid  )*136 + wn2+8*j+grp]);
            b[j][1] = __float_as_uint(Bs[(kk+qid+4)*136 + wn2+8*j+grp]);
        }
        #pragma unroll
        for (int j = 0; j < 4; j++) mma8(acc[j], a, b[j]);
    }
}

__device__ __forceinline__ void stage_nn(float* Bs, const float4* pre, int br, int bc){
    #pragma unroll
    for (int i = 0; i < 4; i++) {
        float4 v;
        v.x = cf(pre[i].x); v.y = cf(pre[i].y);
        v.z = cf(pre[i].z); v.w = cf(pre[i].w);
        *(float4*)&Bs[br*136 + bc + 4*i] = v;
    }
}

__device__ __forceinline__ void stage_tb_h(float* Bs, const float4* pre, int bn, int bk0){
    #pragma unroll
    for (int i = 0; i < 2; i++) {
        const int k = bk0 + 4*i;
        Bs[(k+0)*136 + bn] = cf(pre[i].x);
        Bs[(k+1)*136 + bn] = cf(pre[i].y);
        Bs[(k+2)*136 + bn] = cf(pre[i].z);
        Bs[(k+3)*136 + bn] = cf(pre[i].w);
    }
}

// NN with contiguous weight B[k][n] (ldb row stride), K multiple of 32
__device__ __forceinline__ void gemm_w(
    const float* __restrict__ At, const float* __restrict__ Bg, int ldb, int K,
    float acc[8][4], float* __restrict__ BsBase,
    int wm, int wn, int grp, int qid, int t)
{
    const int br = t >> 3, bc = (t & 7) * 16;
    const float* Bp = Bg + (size_t)br * ldb + bc;
    float4 pre[4];
    #pragma unroll
    for (int i = 0; i < 4; i++) pre[i] = *(const float4*)(Bp + 4*i);
    stage_nn(BsBase, pre, br, bc);
    const int nk = K / 32;
    for (int c = 0; c < nk; c++) {
        __syncthreads();
        if (c + 1 < nk) {
            const float* Bp2 = Bp + (size_t)(c + 1) * 32 * ldb;
            #pragma unroll
            for (int i = 0; i < 4; i++) pre[i] = *(const float4*)(Bp2 + 4*i);
        }
        frag_compute(At, BsBase + (c & 1) * BSW, acc, wm, wn, grp, qid, c * 32);
        if (c + 1 < nk) stage_nn(BsBase + ((c + 1) & 1) * BSW, pre, br, bc);
    }
}

// TRANSB over in-rows, half width (64 kv rows): B row = concat row (row0+bn)
// Staging: 64 rows x 32 dims per chunk; thread bn = t>>2, dims (t&3)*8 .. +7
__device__ __forceinline__ void gemm_tb_h(
    const float* __restrict__ At,
    const float* __restrict__ tensor, const float* __restrict__ latents,
    int bt, int row0, int validN, float acc[4][4], float* __restrict__ BsBase,
    int wm, int wn2, int grp, int qid, int t)
{
    const int bn = t >> 2, bk0 = (t & 3) * 8;
    const bool v = bn < validN;
    const float* Bp = row_ptr(tensor, latents, bt, row0 + (v ? bn : 0)) + bk0;
    float4 pre[2];
    #pragma unroll
    for (int i = 0; i < 2; i++)
        pre[i] = v ? *(const float4*)(Bp + 4*i) : make_float4(0.f,0.f,0.f,0.f);
    stage_tb_h(BsBase, pre, bn, bk0);
    for (int c = 0; c < DIMM; c += 32) {
        __syncthreads();
        if (c + 32 < DIMM) {
            #pragma unroll
            for (int i = 0; i < 2; i++)
                pre[i] = v ? *(const float4*)(Bp + (c + 32) + 4*i)
                           : make_float4(0.f,0.f,0.f,0.f);
        }
        frag_compute_h(At, BsBase + ((c >> 5) & 1) * BSW, acc, wm, wn2, grp, qid, c);
        if (c + 32 < DIMM) stage_tb_h(BsBase + (((c >> 5) + 1) & 1) * BSW, pre, bn, bk0);
    }
}

// NN over in-rows: B row = concat row (row0 + c + br), K = kv count (mult of 32)
__device__ __forceinline__ void gemm_nn_in(
    const float* __restrict__ At,
    const float* __restrict__ tensor, const float* __restrict__ latents,
    int bt, int row0, int K, float acc[8][4], float* __restrict__ BsBase,
    int wm, int wn, int grp, int qid, int t)
{
    const int br = t >> 3, bc = (t & 7) * 16;
    float4 pre[4];
    {
        const float* Bp = row_ptr(tensor, latents, bt, row0 + br) + bc;
        #pragma unroll
        for (int i = 0; i < 4; i++) pre[i] = *(const float4*)(Bp + 4*i);
    }
    stage_nn(BsBase, pre, br, bc);
    for (int c = 0; c < K; c += 32) {
        __syncthreads();
        if (c + 32 < K) {
            const float* Bp2 = row_ptr(tensor, latents, bt, row0 + c + 32 + br) + bc;
            #pragma unroll
            for (int i = 0; i < 4; i++) pre[i] = *(const float4*)(Bp2 + 4*i);
        }
        frag_compute(At, BsBase + ((c >> 5) & 1) * BSW, acc, wm, wn, grp, qid, c);
        if (c + 32 < K) stage_nn(BsBase + (((c >> 5) + 1) & 1) * BSW, pre, br, bc);
    }
}

// ===========================================================================
// k_flash: grid 256 = (bt,h,half), tf32, double-buffered B, spill-free S phase.
// ===========================================================================
#define FLASH_WORDS (9216 + 9216 + 2*BSW + 192)
#define FLASH_SMEM  (FLASH_WORDS * 4)

__global__ void __launch_bounds__(256, 2) k_flash(
    const float* __restrict__ tensor, const float* __restrict__ latents)
{
    extern __shared__ float sm[];
    float* QWt   = sm;                    // [128][72]
    float* SXt   = sm + 9216;             // staging / S / P [128][72]
    float* Bs    = sm + 2*9216;           // [2][32][136]
    float* m_run = Bs + 2*BSW;            // [64]
    float* l_run = m_run + 64;
    float* rsc   = l_run + 64;

    const int zz = blockIdx.x;
    const int z = zz >> 1, half = zz & 1;
    const int bt = z >> 3, h = z & 7;
    const int kvbase = half * KVHALF;

    const int t = threadIdx.x, warp = t >> 5, lane = t & 31;
    const int grp = lane >> 2, qid = lane & 3;
    const int wm = (warp & 3) * 16;
    const int wn = (warp >> 2) * 64;      // full-width N offset
    const int wn2 = (warp >> 2) * 32;     // half-width N offset

    if (t < 64) { m_run[t] = -INFINITY; l_run[t] = 0.f; }

    // stage latents[bt] (64x128) transposed -> SXt[k][r]
    {
        const int r = t >> 2, k0 = (t & 3) * 32;
        const float* Lp = latents + (size_t)bt * NL * DIMM + (size_t)r * DIMM + k0;
        #pragma unroll
        for (int i = 0; i < 8; i++) {
            float4 v = *(const float4*)(Lp + 4*i);
            const int k = k0 + 4*i;
            SXt[(k+0)*72 + r] = cf(v.x);
            SXt[(k+1)*72 + r] = cf(v.y);
            SXt[(k+2)*72 + r] = cf(v.z);
            SXt[(k+3)*72 + r] = cf(v.w);
        }
    }
    __syncthreads();

    // QW = lat @ M_h
    {
        float qacc[8][4];
        #pragma unroll
        for (int j = 0; j < 8; j++)
            #pragma unroll
            for (int i = 0; i < 4; i++) qacc[j][i] = 0.f;
        gemm_w(SXt, g_m + (size_t)h * DIMM * DIMM, DIMM, DIMM,
               qacc, Bs, wm, wn, grp, qid, t);
        #pragma unroll
        for (int j = 0; j < 8; j++) {
            const int c = wn + 8*j + 2*qid;
            QWt[(c  )*72 + wm+grp  ] = cf(qacc[j][0]);
            QWt[(c+1)*72 + wm+grp  ] = cf(qacc[j][1]);
            QWt[(c  )*72 + wm+grp+8] = cf(qacc[j][2]);
            QWt[(c+1)*72 + wm+grp+8] = cf(qacc[j][3]);
        }
    }

    float O[8][4];
    #pragma unroll
    for (int j = 0; j < 8; j++)
        #pragma unroll
        for (int i = 0; i < 4; i++) O[j][i] = 0.f;

    for (int kv0 = 0; kv0 < KVHALF; kv0 += 128) {
        const int valid = (KVHALF - kv0 < 128) ? (KVHALF - kv0) : 128;  // 128 or 32

        // S block = QW @ in_blk^T in two N=64 halves (16-reg sacc, no spills)
        #pragma unroll
        for (int hn = 0; hn < 2; hn++) {
            const int validh = valid - hn * 64;
            if (validh > 0) {
                const int vh = validh < 64 ? validh : 64;
                float sacc[4][4];
                #pragma unroll
                for (int j = 0; j < 4; j++)
                    #pragma unroll
                    for (int i = 0; i < 4; i++) sacc[j][i] = 0.f;
                __syncthreads();   // Bs reuse fence (prev phase / prev half)
                gemm_tb_h(QWt, tensor, latents, bt, kvbase + kv0 + hn * 64, vh,
                          sacc, Bs, wm, wn2, grp, qid, t);
                #pragma unroll
                for (int j = 0; j < 4; j++) {
                    const int c = hn * 64 + wn2 + 8*j + 2*qid;
                    if (c < valid) {
                        SXt[(c  )*72 + wm+grp  ] = sacc[j][0];
                        SXt[(c  )*72 + wm+grp+8] = sacc[j][2];
                    }
                    if (c + 1 < valid) {
                        SXt[(c+1)*72 + wm+grp  ] = sacc[j][1];
                        SXt[(c+1)*72 + wm+grp+8] = sacc[j][3];
                    }
                }
            }
        }
        __syncthreads();

        // online softmax: 4 threads per row, interleaved columns (bank-clean)
        {
            const int row = t >> 2, part = t & 3;
            const float mo = m_run[row];
            float mx = mo;
            #pragma unroll 8
            for (int i = 0; i < 32; i++) {
                const int c = part + 4*i;
                if (c < valid) mx = fmaxf(mx, SXt[c*72 + row]);
            }
            mx = fmaxf(mx, __shfl_xor_sync(0xffffffffu, mx, 1));
            mx = fmaxf(mx, __shfl_xor_sync(0xffffffffu, mx, 2));
            float s = 0.f;
            #pragma unroll 8
            for (int i = 0; i < 32; i++) {
                const int c = part + 4*i;
                if (c < valid) {
                    const float e = __expf(SXt[c*72 + row] - mx);
                    SXt[c*72 + row] = cf(e);
                    s += e;
                }
            }
            s += __shfl_xor_sync(0xffffffffu, s, 1);
            s += __shfl_xor_sync(0xffffffffu, s, 2);
            if (part == 0) {
                const float scale = __expf(mo - mx);
                l_run[row] = l_run[row] * scale + s;
                m_run[row] = mx;
                rsc[row]   = scale;
            }
        }
        __syncthreads();

        // rescale O, then O += P @ in_blk
        {
            const float s0 = rsc[wm+grp], s1 = rsc[wm+grp+8];
            #pragma unroll
            for (int j = 0; j < 8; j++) {
                O[j][0] *= s0; O[j][1] *= s0;
                O[j][2] *= s1; O[j][3] *= s1;
            }
        }
        gemm_nn_in(SXt, tensor, latents, bt, kvbase + kv0, valid,
                   O, Bs, wm, wn, grp, qid, t);
        __syncthreads();
    }

    if (t < 64) g_ml2[(size_t)zz * NL + t] = make_float2(m_run[t], l_run[t]);
    float* P = g_po + (size_t)zz * NL * DIMM;
    #pragma unroll
    for (int j = 0; j < 8; j++) {
        const int c = wn + 8*j + 2*qid;
        *(float2*)&P[(size_t)(wm+grp  ) * DIMM + c] = make_float2(O[j][0], O[j][1]);
        *(float2*)&P[(size_t)(wm+grp+8) * DIMM + c] = make_float2(O[j][2], O[j][3]);
    }
}

// ===========================================================================
// fp32 64x64 cores for split-K weight precompute (proven)
// ===========================================================================
__device__ __forceinline__ void f32_nn_core(
    const float* __restrict__ A, const float* __restrict__ B, float* __restrict__ C,
    int lda, int ldb, int ldc, int K, float alpha, int m0, int n0)
{
    __shared__ float As[16][68];
    __shared__ float Bsb[16][68];
    const int t  = threadIdx.x;
    const int tx = t & 15, ty = t >> 4;
    const int am = t >> 2, ak = (t & 3) << 2;
    const int bk = t >> 4, bn = (t & 15) << 2;
    const float* Ap = A + (size_t)(m0 + am) * lda + ak;
    const float* Bp = B + (size_t)bk * ldb + n0 + bn;
    float acc[4][4] = {};
    for (int kb = 0; kb < K; kb += 16) {
        float4 a = *(const float4*)(Ap + kb);
        float4 b = *(const float4*)(Bp + (size_t)kb * ldb);
        As[ak+0][am] = a.x; As[ak+1][am] = a.y; As[ak+2][am] = a.z; As[ak+3][am] = a.w;
        *(float4*)&Bsb[bk][bn] = b;
        __syncthreads();
        #pragma unroll
        for (int k = 0; k < 16; ++k) {
            float4 av = *(const float4*)&As[k][ty << 2];
            float4 bv = *(const float4*)&Bsb[k][tx << 2];
            acc[0][0] += av.x*bv.x; acc[0][1] += av.x*bv.y; acc[0][2] += av.x*bv.z; acc[0][3] += av.x*bv.w;
            acc[1][0] += av.y*bv.x; acc[1][1] += av.y*bv.y; acc[1][2] += av.y*bv.z; acc[1][3] += av.y*bv.w;
            acc[2][0] += av.z*bv.x; acc[2][1] += av.z*bv.y; acc[2][2] += av.z*bv.z; acc[2][3] += av.z*bv.w;
            acc[3][0] += av.w*bv.x; acc[3][1] += av.w*bv.y; acc[3][2] += av.w*bv.z; acc[3][3] += av.w*bv.w;
        }
        __syncthreads();
    }
    #pragma unroll
    for (int i = 0; i < 4; ++i) {
        float4 r;
        r.x = acc[i][0]*alpha; r.y = acc[i][1]*alpha; r.z = acc[i][2]*alpha; r.w = acc[i][3]*alpha;
        *(float4*)&C[(size_t)(m0 + (ty << 2) + i) * ldc + n0 + (tx << 2)] = r;
    }
}

__device__ __forceinline__ void f32_nt_core(
    const float* __restrict__ A, const float* __restrict__ Bm, float* __restrict__ C,
    int lda, int ldb, int ldc, int K, float alpha, int m0, int n0)
{
    __shared__ float As[16][68];
    __shared__ float Bsb[16][68];
    const int t  = threadIdx.x;
    const int tx = t & 15, ty = t >> 4;
    const int am = t >> 2, ak = (t & 3) << 2;
    const int bn = t >> 2, bq = (t & 3) << 2;
    const float* Ap = A  + (size_t)(m0 + am) * lda + ak;
    const float* Bp = Bm + (size_t)(n0 + bn) * ldb + bq;
    float acc[4][4] = {};
    for (int kb = 0; kb < K; kb += 16) {
        float4 a = *(const float4*)(Ap + kb);
        float4 b = *(const float4*)(Bp + kb);
        As[ak+0][am] = a.x; As[ak+1][am] = a.y; As[ak+2][am] = a.z; As[ak+3][am] = a.w;
        Bsb[bq+0][bn] = b.x; Bsb[bq+1][bn] = b.y; Bsb[bq+2][bn] = b.z; Bsb[bq+3][bn] = b.w;
        __syncthreads();
        #pragma unroll
        for (int k = 0; k < 16; ++k) {
            float4 av = *(const float4*)&As[k][ty << 2];
            float4 bv = *(const float4*)&Bsb[k][tx << 2];
            acc[0][0] += av.x*bv.x; acc[0][1] += av.x*bv.y; acc[0][2] += av.x*bv.z; acc[0][3] += av.x*bv.w;
            acc[1][0] += av.y*bv.x; acc[1][1] += av.y*bv.y; acc[1][2] += av.y*bv.z; acc[1][3] += av.y*bv.w;
            acc[2][0] += av.z*bv.x; acc[2][1] += av.z*bv.y; acc[2][2] += av.z*bv.z; acc[2][3] += av.z*bv.w;
            acc[3][0] += av.w*bv.x; acc[3][1] += av.w*bv.y; acc[3][2] += av.w*bv.z; acc[3][3] += av.w*bv.w;
        }
        __syncthreads();
    }
    #pragma unroll
    for (int i = 0; i < 4; ++i) {
        float4 r;
        r.x = acc[i][0]*alpha; r.y = acc[i][1]*alpha; r.z = acc[i][2]*alpha; r.w = acc[i][3]*alpha;
        *(float4*)&C[(size_t)(m0 + (ty << 2) + i) * ldc + n0 + (tx << 2)] = r;
    }
}

__global__ void k_prep_part(const float* __restrict__ Wq, const float* __restrict__ Wkv,
                            const float* __restrict__ Wo)
{
    const int b = blockIdx.x;
    const int isN = b >> 7, idx = b & 127;
    const int h = idx >> 4, sub = (idx >> 2) & 3, ks = idx & 3;
    const int m0 = (sub >> 1) * 64, n0 = (sub & 1) * 64, k0 = ks * 64;
    float* C = g_pp + ((size_t)(isN * 4 + ks) * 8 + h) * (DIMM * DIMM);
    if (!isN)
        f32_nt_core(Wq + h * 256 + k0, Wkv + h * 256 + k0, C,
                    INNER, 2 * INNER, DIMM, 64, 1.0f, m0, n0);
    else
        f32_nn_core(Wkv + INNER + h * 256 + k0, Wo + ((size_t)h * 256 + k0) * DIMM, C,
                    2 * INNER, DIMM, DIMM, 64, 1.0f, m0, n0);
}

__global__ void k_prep_red()
{
    const int i = blockIdx.x * 256 + threadIdx.x;   // float4 idx, 65536 total
    const int isN = i >> 15, j = i & 32767;
    const int h = j >> 12, e = j & 4095;
    const float4* pp = (const float4*)g_pp;
    float4 r = make_float4(0.f, 0.f, 0.f, 0.f);
    #pragma unroll
    for (int ks = 0; ks < 4; ks++) {
        float4 a = pp[((size_t)(isN * 4 + ks) * 8 + h) * 4096 + e];
        r.x += a.x; r.y += a.y; r.z += a.z; r.w += a.w;
    }
    if (!isN) {
        r.x *= QSCALE; r.y *= QSCALE; r.z *= QSCALE; r.w *= QSCALE;
        ((float4*)g_m)[(size_t)h * 4096 + e] = r;
    } else {
        ((float4*)g_n)[(size_t)h * 4096 + e] = r;
    }
}

// ===========================================================================
// k_final_part (proven): per (h, bt) partial_h = PI_h @ N_h with flash-combine
// fused into the A loader. 128 threads, grid (8, 16).
// ===========================================================================
__global__ void __launch_bounds__(128) k_final_part()
{
    __shared__ float As[32][72];
    __shared__ float Bsb[32][136];
    const int h = blockIdx.x, bt = blockIdx.y;
    const int z = bt * HEADS + h;
    const float* B = g_n + (size_t)h * DIMM * DIMM;
    float*       C = g_fp + (size_t)z * NL * DIMM;

    const int t    = threadIdx.x;
    const int warp = t >> 5, lane = t & 31;
    const int grp  = lane >> 2, qid = lane & 3;
    const int wm   = (warp & 1) * 32, wn = (warp >> 1) * 64;

    const int arow = t >> 1, ak0 = (t & 1) * 16;

    float2 ml0 = g_ml2[(size_t)(z*2  ) * NL + arow];
    float2 ml1 = g_ml2[(size_t)(z*2+1) * NL + arow];
    const float mm = fmaxf(ml0.x, ml1.x);
    const float a0 = __expf(ml0.x - mm), a1 = __expf(ml1.x - mm);
    const float il = 1.0f / (ml0.y * a0 + ml1.y * a1);
    const float e0 = a0 * il, e1 = a1 * il;

    const float* O0 = g_po + (size_t)(z*2  ) * NL * DIMM + (size_t)arow * DIMM + ak0;
    const float* O1 = g_po + (size_t)(z*2+1) * NL * DIMM + (size_t)arow * DIMM + ak0;
    const int brow = t >> 2, bcol = (t & 3) * 32;
    const float* Bp = B + (size_t)brow * DIMM + bcol;

    float acc[2][8][4];
    #pragma unroll
    for (int f = 0; f < 2; f++)
        #pragma unroll
        for (int j = 0; j < 8; j++)
            #pragma unroll
            for (int i = 0; i < 4; i++) acc[f][j][i] = 0.f;

    float4 o0[4], o1[4], br[8];
    #pragma unroll
    for (int i = 0; i < 4; i++) {
        o0[i] = *(const float4*)(O0 + 4*i);
        o1[i] = *(const float4*)(O1 + 4*i);
    }
    #pragma unroll
    for (int i = 0; i < 8; i++) br[i] = *(const float4*)(Bp + 4*i);

    const int nk = DIMM / 32;   // 4
    for (int c = 0; c < nk; c++) {
        #pragma unroll
        for (int i = 0; i < 4; i++) {
            const int kc = ak0 + 4*i;
            As[kc+0][arow] = cf(e0*o0[i].x + e1*o1[i].x);
            As[kc+1][arow] = cf(e0*o0[i].y + e1*o1[i].y);
            As[kc+2][arow] = cf(e0*o0[i].z + e1*o1[i].z);
            As[kc+3][arow] = cf(e0*o0[i].w + e1*o1[i].w);
        }
        #pragma unroll
        for (int i = 0; i < 8; i++) {
            float4 v;
            v.x = cf(br[i].x); v.y = cf(br[i].y);
            v.z = cf(br[i].z); v.w = cf(br[i].w);
            *(float4*)&Bsb[brow][bcol + 4*i] = v;
        }
        __syncthreads();
        if (c + 1 < nk) {
            #pragma unroll
            for (int i = 0; i < 4; i++) {
                o0[i] = *(const float4*)(O0 + (c+1)*32 + 4*i);
                o1[i] = *(const float4*)(O1 + (c+1)*32 + 4*i);
            }
            const float* Bp2 = Bp + (size_t)(c + 1) * 32 * DIMM;
            #pragma unroll
            for (int i = 0; i < 8; i++) br[i] = *(const float4*)(Bp2 + 4*i);
        }
        #pragma unroll
        for (int kk = 0; kk < 32; kk += 8) {
            unsigned a[2][4], b[8][2];
            #pragma unroll
            for (int f = 0; f < 2; f++) {
                a[f][0] = __float_as_uint(As[kk+qid  ][wm+16*f+grp  ]);
                a[f][1] = __float_as_uint(As[kk+qid  ][wm+16*f+grp+8]);
                a[f][2] = __float_as_uint(As[kk+qid+4][wm+16*f+grp  ]);
                a[f][3] = __float_as_uint(As[kk+qid+4][wm+16*f+grp+8]);
            }
            #pragma unroll
            for (int j = 0; j < 8; j++) {
                b[j][0] = __float_as_uint(Bsb[kk+qid  ][wn+8*j+grp]);
                b[j][1] = __float_as_uint(Bsb[kk+qid+4][wn+8*j+grp]);
            }
            #pragma unroll
            for (int f = 0; f < 2; f++)
                #pragma unroll
                for (int j = 0; j < 8; j++) mma8(acc[f][j], a[f], b[j]);
        }
        __syncthreads();
    }
    #pragma unroll
    for (int f = 0; f < 2; f++) {
        const int r0 = wm + 16*f + grp;
        #pragma unroll
        for (int j = 0; j < 8; j++) {
            const int col = wn + 8*j + 2*qid;
            *(float2*)&C[(size_t)r0 * DIMM + col] = make_float2(acc[f][j][0], acc[f][j][1]);
            *(float2*)&C[(size_t)(r0+8) * DIMM + col] = make_float2(acc[f][j][2], acc[f][j][3]);
        }
    }
}

// reduce 8 per-head partials -> out
__global__ void k_final_red(float* __restrict__ out)
{
    const int i = blockIdx.x * 256 + threadIdx.x;   // float4 index, 32768 total
    const int bt = i >> 11, inner = i & 2047;
    const float4* fp = (const float4*)g_fp;
    float4 r = make_float4(0.f, 0.f, 0.f, 0.f);
    #pragma unroll
    for (int h = 0; h < 8; h++) {
        float4 a = fp[((size_t)bt * 8 + h) * 2048 + inner];
        r.x += a.x; r.y += a.y; r.z += a.z; r.w += a.w;
    }
    ((float4*)out)[i] = r;
}

// ---------------------------------------------------------------------------

extern "C" void kernel_launch(void* const* d_in, const int* in_sizes, int n_in,
                              void* d_out, int out_size)
{
    const float* tensor  = (const float*)d_in[0];
    const float* latents = (const float*)d_in[1];
    const float* Wq      = (const float*)d_in[2];
    const float* Wkv     = (const float*)d_in[3];
    const float* Wo      = (const float*)d_in[4];
    float*       out     = (float*)d_out;

    (void)in_sizes; (void)n_in; (void)out_size;

    cudaFuncSetAttribute(k_flash, cudaFuncAttributeMaxDynamicSharedMemorySize, FLASH_SMEM);

    k_prep_part <<<256, 256>>>(Wq, Wkv, Wo);
    k_prep_red  <<<256, 256>>>();
    k_flash     <<<2 * BTT * HEADS, 256, FLASH_SMEM>>>(tensor, latents);
    k_final_part<<<dim3(HEADS, BTT), 128>>>();
    k_final_red <<<(BTT * NL * DIMM / 4) / 256, 256>>>(out);
}

// round 10
// speedup vs baseline: 1.6178x; 1.0204x over previous
#include <cuda_runtime.h>
#include <math.h>

// Problem constants
#define BTT     16
#define NM      1024
#define NL      64
#define NKV     1088
#define DIMM    128
#define HEADS   8
#define INNER   2048
#define QSCALE  0.08838834764831845f   // 128^-0.5
#define KVHALF  544

// Static device scratch
static __device__ float  g_pp[2 * 4 * 8 * DIMM * DIMM];       // split-K prep partials
static __device__ float  g_m [HEADS * DIMM * DIMM];           // M_h = scale*Wq_h@Wk_h^T
static __device__ float  g_n [HEADS * DIMM * DIMM];           // N_h = Wv_h@Wo_h
static __device__ float  g_po[2 * BTT * HEADS * NL * DIMM];   // un-normalized O halves
static __device__ float2 g_ml2[2 * BTT * HEADS * NL];         // (m, l) per half per row
static __device__ float  g_fp [BTT * HEADS * NL * DIMM];      // per-head partials of out

// fp32 -> tf32 round-to-nearest
__device__ __forceinline__ float cf(float x){
    unsigned u; asm("cvt.rna.tf32.f32 %0, %1;" : "=r"(u) : "f"(x));
    return __uint_as_float(u);
}

__device__ __forceinline__ void mma8(float* d, const unsigned* a, const unsigned* b){
    asm volatile("mma.sync.aligned.m16n8k8.row.col.f32.tf32.tf32.f32 "
        "{%0,%1,%2,%3}, {%4,%5,%6,%7}, {%8,%9}, {%0,%1,%2,%3};"
        : "+f"(d[0]), "+f"(d[1]), "+f"(d[2]), "+f"(d[3])
        : "r"(a[0]), "r"(a[1]), "r"(a[2]), "r"(a[3]), "r"(b[0]), "r"(b[1]));
}

// row r of concat(tensor[bt], latents[bt])
__device__ __forceinline__ const float* row_ptr(
    const float* __restrict__ tensor, const float* __restrict__ latents, int bt, int r)
{
    return (r < NM) ? tensor  + ((size_t)bt * NM + r)        * DIMM
                    : latents + ((size_t)bt * NL + (r - NM)) * DIMM;
}

// ===========================================================================
// Flash building blocks: 256 threads (8 warps).
// A resident in smem At[k][72] (tf32). B double-buffered [2][32][136].
// ===========================================================================
#define BSW 4352   // words per Bs buffer (32*136)

// full-width fragment compute: warp tile 16x64 (acc[8][4])
__device__ __forceinline__ void frag_compute(
    const float* __restrict__ At, const float* __restrict__ Bs,
    float acc[8][4], int wm, int wn, int grp, int qid, int kbase)
{
    #pragma unroll
    for (int kk = 0; kk < 32; kk += 8) {
        unsigned a[4], b[8][2];
        const int k0 = kbase + kk;
        a[0] = __float_as_uint(At[(k0+qid  )*72 + wm+grp  ]);
        a[1] = __float_as_uint(At[(k0+qid  )*72 + wm+grp+8]);
        a[2] = __float_as_uint(At[(k0+qid+4)*72 + wm+grp  ]);
        a[3] = __float_as_uint(At[(k0+qid+4)*72 + wm+grp+8]);
        #pragma unroll
        for (int j = 0; j < 8; j++) {
            b[j][0] = __float_as_uint(Bs[(kk+qid  )*136 + wn+8*j+grp]);
            b[j][1] = __float_as_uint(Bs[(kk+qid+4)*136 + wn+8*j+grp]);
        }
        #pragma unroll
        for (int j = 0; j < 8; j++) mma8(acc[j], a, b[j]);
    }
}

// half-width fragment compute: warp tile 16x32 (acc[4][4]) — lower reg pressure
__device__ __forceinline__ void frag_compute_h(
    const float* __restrict__ At, const float* __restrict__ Bs,
    float acc[4][4], int wm, int wn2, int grp, int qid, int kbase)
{
    #pragma unroll
    for (int kk = 0; kk < 32; kk += 8) {
        unsigned a[4], b[4][2];
        const int k0 = kbase + kk;
        a[0] = __float_as_uint(At[(k0+qid  )*72 + wm+grp  ]);
        a[1] = __float_as_uint(At[(k0+qid  )*72 + wm+grp+8]);
        a[2] = __float_as_uint(At[(k0+qid+4)*72 + wm+grp  ]);
        a[3] = __float_as_uint(At[(k0+qid+4)*72 + wm+grp+8]);
        #pragma unroll
        for (int j = 0; j < 4; j++) {
            b[j][0] = __float_as_uint(Bs[(kk+qid  )*136 + wn2+8*j+grp]);
            b[j][1] = __float_as_uint(Bs[(kk+qid+4)*136 + wn2+8*j+grp]);
        }
        #pragma unroll
        for (int j = 0; j < 4; j++) mma8(acc[j], a, b[j]);
    }
}

__device__ __forceinline__ void stage_nn(float* Bs, const float4* pre, int br, int bc){
    #pragma unroll
    for (int i = 0; i < 4; i++) {
        float4 v;
        v.x = cf(pre[i].x); v.y = cf(pre[i].y);
        v.z = cf(pre[i].z); v.w = cf(pre[i].w);
        *(float4*)&Bs[br*136 + bc + 4*i] = v;
    }
}

__device__ __forceinline__ void stage_tb_h(float* Bs, const float4* pre, int bn, int bk0){
    #pragma unroll
    for (int i = 0; i < 2; i++) {
        const int k = bk0 + 4*i;
        Bs[(k+0)*136 + bn] = cf(pre[i].x);
        Bs[(k+1)*136 + bn] = cf(pre[i].y);
        Bs[(k+2)*136 + bn] = cf(pre[i].z);
        Bs[(k+3)*136 + bn] = cf(pre[i].w);
    }
}

// NN with contiguous weight B[k][n] (ldb row stride), K multiple of 32
__device__ __forceinline__ void gemm_w(
    const float* __restrict__ At, const float* __restrict__ Bg, int ldb, int K,
    float acc[8][4], float* __restrict__ BsBase,
    int wm, int wn, int grp, int qid, int t)
{
    const int br = t >> 3, bc = (t & 7) * 16;
    const float* Bp = Bg + (size_t)br * ldb + bc;
    float4 pre[4];
    #pragma unroll
    for (int i = 0; i < 4; i++) pre[i] = *(const float4*)(Bp + 4*i);
    stage_nn(BsBase, pre, br, bc);
    const int nk = K / 32;
    for (int c = 0; c < nk; c++) {
        __syncthreads();
        if (c + 1 < nk) {
            const float* Bp2 = Bp + (size_t)(c + 1) * 32 * ldb;
            #pragma unroll
            for (int i = 0; i < 4; i++) pre[i] = *(const float4*)(Bp2 + 4*i);
        }
        frag_compute(At, BsBase + (c & 1) * BSW, acc, wm, wn, grp, qid, c * 32);
        if (c + 1 < nk) stage_nn(BsBase + ((c + 1) & 1) * BSW, pre, br, bc);
    }
}

// TRANSB over in-rows, half width (64 kv rows): B row = concat row (row0+bn)
__device__ __forceinline__ void gemm_tb_h(
    const float* __restrict__ At,
    const float* __restrict__ tensor, const float* __restrict__ latents,
    int bt, int row0, int validN, float acc[4][4], float* __restrict__ BsBase,
    int wm, int wn2, int grp, int qid, int t)
{
    const int bn = t >> 2, bk0 = (t & 3) * 8;
    const bool v = bn < validN;
    const float* Bp = row_ptr(tensor, latents, bt, row0 + (v ? bn : 0)) + bk0;
    float4 pre[2];
    #pragma unroll
    for (int i = 0; i < 2; i++)
        pre[i] = v ? *(const float4*)(Bp + 4*i) : make_float4(0.f,0.f,0.f,0.f);
    stage_tb_h(BsBase, pre, bn, bk0);
    for (int c = 0; c < DIMM; c += 32) {
        __syncthreads();
        if (c + 32 < DIMM) {
            #pragma unroll
            for (int i = 0; i < 2; i++)
                pre[i] = v ? *(const float4*)(Bp + (c + 32) + 4*i)
                           : make_float4(0.f,0.f,0.f,0.f);
        }
        frag_compute_h(At, BsBase + ((c >> 5) & 1) * BSW, acc, wm, wn2, grp, qid, c);
        if (c + 32 < DIMM) stage_tb_h(BsBase + (((c >> 5) + 1) & 1) * BSW, pre, bn, bk0);
    }
}

// NN over in-rows: B row = concat row (row0 + c + br), K = kv count (mult of 32)
__device__ __forceinline__ void gemm_nn_in(
    const float* __restrict__ At,
    const float* __restrict__ tensor, const float* __restrict__ latents,
    int bt, int row0, int K, float acc[8][4], float* __restrict__ BsBase,
    int wm, int wn, int grp, int qid, int t)
{
    const int br = t >> 3, bc = (t & 7) * 16;
    float4 pre[4];
    {
        const float* Bp = row_ptr(tensor, latents, bt, row0 + br) + bc;
        #pragma unroll
        for (int i = 0; i < 4; i++) pre[i] = *(const float4*)(Bp + 4*i);
    }
    stage_nn(BsBase, pre, br, bc);
    for (int c = 0; c < K; c += 32) {
        __syncthreads();
        if (c + 32 < K) {
            const float* Bp2 = row_ptr(tensor, latents, bt, row0 + c + 32 + br) + bc;
            #pragma unroll
            for (int i = 0; i < 4; i++) pre[i] = *(const float4*)(Bp2 + 4*i);
        }
        frag_compute(At, BsBase + ((c >> 5) & 1) * BSW, acc, wm, wn, grp, qid, c);
        if (c + 32 < K) stage_nn(BsBase + (((c >> 5) + 1) & 1) * BSW, pre, br, bc);
    }
}

// ===========================================================================
// k_flash: grid 256 = (bt,h,half), tf32, double-buffered B, spill-free S phase.
// ===========================================================================
#define FLASH_WORDS (9216 + 9216 + 2*BSW + 192)
#define FLASH_SMEM  (FLASH_WORDS * 4)

__global__ void __launch_bounds__(256, 2) k_flash(
    const float* __restrict__ tensor, const float* __restrict__ latents)
{
    extern __shared__ float sm[];
    float* QWt   = sm;                    // [128][72]
    float* SXt   = sm + 9216;             // staging / S / P [128][72]
    float* Bs    = sm + 2*9216;           // [2][32][136]
    float* m_run = Bs + 2*BSW;            // [64]
    float* l_run = m_run + 64;
    float* rsc   = l_run + 64;

    const int zz = blockIdx.x;
    const int z = zz >> 1, half = zz & 1;
    const int bt = z >> 3, h = z & 7;
    const int kvbase = half * KVHALF;

    const int t = threadIdx.x, warp = t >> 5, lane = t & 31;
    const int grp = lane >> 2, qid = lane & 3;
    const int wm = (warp & 3) * 16;
    const int wn = (warp >> 2) * 64;      // full-width N offset
    const int wn2 = (warp >> 2) * 32;     // half-width N offset

    if (t < 64) { m_run[t] = -INFINITY; l_run[t] = 0.f; }

    // stage latents[bt] (64x128) transposed -> SXt[k][r]
    {
        const int r = t >> 2, k0 = (t & 3) * 32;
        const float* Lp = latents + (size_t)bt * NL * DIMM + (size_t)r * DIMM + k0;
        #pragma unroll
        for (int i = 0; i < 8; i++) {
            float4 v = *(const float4*)(Lp + 4*i);
            const int k = k0 + 4*i;
            SXt[(k+0)*72 + r] = cf(v.x);
            SXt[(k+1)*72 + r] = cf(v.y);
            SXt[(k+2)*72 + r] = cf(v.z);
            SXt[(k+3)*72 + r] = cf(v.w);
        }
    }
    __syncthreads();

    // QW = lat @ M_h
    {
        float qacc[8][4];
        #pragma unroll
        for (int j = 0; j < 8; j++)
            #pragma unroll
            for (int i = 0; i < 4; i++) qacc[j][i] = 0.f;
        gemm_w(SXt, g_m + (size_t)h * DIMM * DIMM, DIMM, DIMM,
               qacc, Bs, wm, wn, grp, qid, t);
        #pragma unroll
        for (int j = 0; j < 8; j++) {
            const int c = wn + 8*j + 2*qid;
            QWt[(c  )*72 + wm+grp  ] = cf(qacc[j][0]);
            QWt[(c+1)*72 + wm+grp  ] = cf(qacc[j][1]);
            QWt[(c  )*72 + wm+grp+8] = cf(qacc[j][2]);
            QWt[(c+1)*72 + wm+grp+8] = cf(qacc[j][3]);
        }
    }
    // NOTE: no sync needed here — the first S-chunk's top barrier orders the
    // QWt epilogue stores of all warps before any fragment read, and staging
    // into Bs buffer 0 is safe (all warps passed the last chunk's barrier,
    // which postdates every buffer-0 read of the QW phase).

    float O[8][4];
    #pragma unroll
    for (int j = 0; j < 8; j++)
        #pragma unroll
        for (int i = 0; i < 4; i++) O[j][i] = 0.f;

    for (int kv0 = 0; kv0 < KVHALF; kv0 += 128) {
        const int valid = (KVHALF - kv0 < 128) ? (KVHALF - kv0) : 128;  // 128 or 32

        // S block = QW @ in_blk^T in two N=64 halves (16-reg sacc, no spills)
        #pragma unroll
        for (int hn = 0; hn < 2; hn++) {
            const int validh = valid - hn * 64;
            if (validh > 0) {
                const int vh = validh < 64 ? validh : 64;
                float sacc[4][4];
                #pragma unroll
                for (int j = 0; j < 4; j++)
                    #pragma unroll
                    for (int i = 0; i < 4; i++) sacc[j][i] = 0.f;
                gemm_tb_h(QWt, tensor, latents, bt, kvbase + kv0 + hn * 64, vh,
                          sacc, Bs, wm, wn2, grp, qid, t);
                #pragma unroll
                for (int j = 0; j < 4; j++) {
                    const int c = hn * 64 + wn2 + 8*j + 2*qid;
                    if (c < valid) {
                        SXt[(c  )*72 + wm+grp  ] = sacc[j][0];
                        SXt[(c  )*72 + wm+grp+8] = sacc[j][2];
                    }
                    if (c + 1 < valid) {
                        SXt[(c+1)*72 + wm+grp  ] = sacc[j][1];
                        SXt[(c+1)*72 + wm+grp+8] = sacc[j][3];
                    }
                }
            }
        }
        __syncthreads();

        // online softmax: 4 threads per row, interleaved columns (bank-clean)
        {
            const int row = t >> 2, part = t & 3;
            const float mo = m_run[row];
            float mx = mo;
            #pragma unroll 8
            for (int i = 0; i < 32; i++) {
                const int c = part + 4*i;
                if (c < valid) mx = fmaxf(mx, SXt[c*72 + row]);
            }
            mx = fmaxf(mx, __shfl_xor_sync(0xffffffffu, mx, 1));
            mx = fmaxf(mx, __shfl_xor_sync(0xffffffffu, mx, 2));
            float s = 0.f;
            #pragma unroll 8
            for (int i = 0; i < 32; i++) {
                const int c = part + 4*i;
                if (c < valid) {
                    const float e = __expf(SXt[c*72 + row] - mx);
                    SXt[c*72 + row] = cf(e);
                    s += e;
                }
            }
            s += __shfl_xor_sync(0xffffffffu, s, 1);
            s += __shfl_xor_sync(0xffffffffu, s, 2);
            if (part == 0) {
                const float scale = __expf(mo - mx);
                l_run[row] = l_run[row] * scale + s;
                m_run[row] = mx;
                rsc[row]   = scale;
            }
        }
        __syncthreads();

        // rescale O, then O += P @ in_blk
        {
            const float s0 = rsc[wm+grp], s1 = rsc[wm+grp+8];
            #pragma unroll
            for (int j = 0; j < 8; j++) {
                O[j][0] *= s0; O[j][1] *= s0;
                O[j][2] *= s1; O[j][3] *= s1;
            }
        }
        gemm_nn_in(SXt, tensor, latents, bt, kvbase + kv0, valid,
                   O, Bs, wm, wn, grp, qid, t);
        __syncthreads();
    }

    if (t < 64) g_ml2[(size_t)zz * NL + t] = make_float2(m_run[t], l_run[t]);
    float* P = g_po + (size_t)zz * NL * DIMM;
    #pragma unroll
    for (int j = 0; j < 8; j++) {
        const int c = wn + 8*j + 2*qid;
        *(float2*)&P[(size_t)(wm+grp  ) * DIMM + c] = make_float2(O[j][0], O[j][1]);
        *(float2*)&P[(size_t)(wm+grp+8) * DIMM + c] = make_float2(O[j][2], O[j][3]);
    }
}

// ===========================================================================
// fp32 64x64 cores for split-K weight precompute (proven)
// ===========================================================================
__device__ __forceinline__ void f32_nn_core(
    const float* __restrict__ A, const float* __restrict__ B, float* __restrict__ C,
    int lda, int ldb, int ldc, int K, float alpha, int m0, int n0)
{
    __shared__ float As[16][68];
    __shared__ float Bsb[16][68];
    const int t  = threadIdx.x;
    const int tx = t & 15, ty = t >> 4;
    const int am = t >> 2, ak = (t & 3) << 2;
    const int bk = t >> 4, bn = (t & 15) << 2;
    const float* Ap = A + (size_t)(m0 + am) * lda + ak;
    const float* Bp = B + (size_t)bk * ldb + n0 + bn;
    float acc[4][4] = {};
    for (int kb = 0; kb < K; kb += 16) {
        float4 a = *(const float4*)(Ap + kb);
        float4 b = *(const float4*)(Bp + (size_t)kb * ldb);
        As[ak+0][am] = a.x; As[ak+1][am] = a.y; As[ak+2][am] = a.z; As[ak+3][am] = a.w;
        *(float4*)&Bsb[bk][bn] = b;
        __syncthreads();
        #pragma unroll
        for (int k = 0; k < 16; ++k) {
            float4 av = *(const float4*)&As[k][ty << 2];
            float4 bv = *(const float4*)&Bsb[k][tx << 2];
            acc[0][0] += av.x*bv.x; acc[0][1] += av.x*bv.y; acc[0][2] += av.x*bv.z; acc[0][3] += av.x*bv.w;
            acc[1][0] += av.y*bv.x; acc[1][1] += av.y*bv.y; acc[1][2] += av.y*bv.z; acc[1][3] += av.y*bv.w;
            acc[2][0] += av.z*bv.x; acc[2][1] += av.z*bv.y; acc[2][2] += av.z*bv.z; acc[2][3] += av.z*bv.w;
            acc[3][0] += av.w*bv.x; acc[3][1] += av.w*bv.y; acc[3][2] += av.w*bv.z; acc[3][3] += av.w*bv.w;
        }
        __syncthreads();
    }
    #pragma unroll
    for (int i = 0; i < 4; ++i) {
        float4 r;
        r.x = acc[i][0]*alpha; r.y = acc[i][1]*alpha; r.z = acc[i][2]*alpha; r.w = acc[i][3]*alpha;
        *(float4*)&C[(size_t)(m0 + (ty << 2) + i) * ldc + n0 + (tx << 2)] = r;
    }
}

__device__ __forceinline__ void f32_nt_core(
    const float* __restrict__ A, const float* __restrict__ Bm, float* __restrict__ C,
    int lda, int ldb, int ldc, int K, float alpha, int m0, int n0)
{
    __shared__ float As[16][68];
    __shared__ float Bsb[16][68];
    const int t  = threadIdx.x;
    const int tx = t & 15, ty = t >> 4;
    const int am = t >> 2, ak = (t & 3) << 2;
    const int bn = t >> 2, bq = (t & 3) << 2;
    const float* Ap = A  + (size_t)(m0 + am) * lda + ak;
    const float* Bp = Bm + (size_t)(n0 + bn) * ldb + bq;
    float acc[4][4] = {};
    for (int kb = 0; kb < K; kb += 16) {
        float4 a = *(const float4*)(Ap + kb);
        float4 b = *(const float4*)(Bp + kb);
        As[ak+0][am] = a.x; As[ak+1][am] = a.y; As[ak+2][am] = a.z; As[ak+3][am] = a.w;
        Bsb[bq+0][bn] = b.x; Bsb[bq+1][bn] = b.y; Bsb[bq+2][bn] = b.z; Bsb[bq+3][bn] = b.w;
        __syncthreads();
        #pragma unroll
        for (int k = 0; k < 16; ++k) {
            float4 av = *(const float4*)&As[k][ty << 2];
            float4 bv = *(const float4*)&Bsb[k][tx << 2];
            acc[0][0] += av.x*bv.x; acc[0][1] += av.x*bv.y; acc[0][2] += av.x*bv.z; acc[0][3] += av.x*bv.w;
            acc[1][0] += av.y*bv.x; acc[1][1] += av.y*bv.y; acc[1][2] += av.y*bv.z; acc[1][3] += av.y*bv.w;
            acc[2][0] += av.z*bv.x; acc[2][1] += av.z*bv.y; acc[2][2] += av.z*bv.z; acc[2][3] += av.z*bv.w;
            acc[3][0] += av.w*bv.x; acc[3][1] += av.w*bv.y; acc[3][2] += av.w*bv.z; acc[3][3] += av.w*bv.w;
        }
        __syncthreads();
    }
    #pragma unroll
    for (int i = 0; i < 4; ++i) {
        float4 r;
        r.x = acc[i][0]*alpha; r.y = acc[i][1]*alpha; r.z = acc[i][2]*alpha; r.w = acc[i][3]*alpha;
        *(float4*)&C[(size_t)(m0 + (ty << 2) + i) * ldc + n0 + (tx << 2)] = r;
    }
}

__global__ void k_prep_part(const float* __restrict__ Wq, const float* __restrict__ Wkv,
                            const float* __restrict__ Wo)
{
    const int b = blockIdx.x;
    const int isN = b >> 7, idx = b & 127;
    const int h = idx >> 4, sub = (idx >> 2) & 3, ks = idx & 3;
    const int m0 = (sub >> 1) * 64, n0 = (sub & 1) * 64, k0 = ks * 64;
    float* C = g_pp + ((size_t)(isN * 4 + ks) * 8 + h) * (DIMM * DIMM);
    if (!isN)
        f32_nt_core(Wq + h * 256 + k0, Wkv + h * 256 + k0, C,
                    INNER, 2 * INNER, DIMM, 64, 1.0f, m0, n0);
    else
        f32_nn_core(Wkv + INNER + h * 256 + k0, Wo + ((size_t)h * 256 + k0) * DIMM, C,
                    2 * INNER, DIMM, DIMM, 64, 1.0f, m0, n0);
}

__global__ void k_prep_red()
{
    const int i = blockIdx.x * 256 + threadIdx.x;   // float4 idx, 65536 total
    const int isN = i >> 15, j = i & 32767;
    const int h = j >> 12, e = j & 4095;
    const float4* pp = (const float4*)g_pp;
    float4 r = make_float4(0.f, 0.f, 0.f, 0.f);
    #pragma unroll
    for (int ks = 0; ks < 4; ks++) {
        float4 a = pp[((size_t)(isN * 4 + ks) * 8 + h) * 4096 + e];
        r.x += a.x; r.y += a.y; r.z += a.z; r.w += a.w;
    }
    if (!isN) {
        r.x *= QSCALE; r.y *= QSCALE; r.z *= QSCALE; r.w *= QSCALE;
        ((float4*)g_m)[(size_t)h * 4096 + e] = r;
    } else {
        ((float4*)g_n)[(size_t)h * 4096 + e] = r;
    }
}

// ===========================================================================
// k_final_part: per (h, bt) partial_h = PI_h @ N_h with flash-combine fused
// into the A loader. NOW 256 threads / 8 warps (warp tile 16x64) for 2x the
// latency hiding; same math and K-order as the proven 128-thread version.
// ===========================================================================
__global__ void __launch_bounds__(256) k_final_part()
{
    __shared__ float As[32][72];
    __shared__ float Bsb[32][136];
    const int h = blockIdx.x, bt = blockIdx.y;
    const int z = bt * HEADS + h;
    const float* B = g_n + (size_t)h * DIMM * DIMM;
    float*       C = g_fp + (size_t)z * NL * DIMM;

    const int t    = threadIdx.x;
    const int warp = t >> 5, lane = t & 31;
    const int grp  = lane >> 2, qid = lane & 3;
    const int wm   = (warp & 3) * 16, wn = (warp >> 2) * 64;

    // A loader: row arow = t>>2 (0..63), k offset ak0 = (t&3)*8 (8 floats)
    const int arow = t >> 2, ak0 = (t & 3) * 8;

    float2 ml0 = g_ml2[(size_t)(z*2  ) * NL + arow];
    float2 ml1 = g_ml2[(size_t)(z*2+1) * NL + arow];
    const float mm = fmaxf(ml0.x, ml1.x);
    const float a0 = __expf(ml0.x - mm), a1 = __expf(ml1.x - mm);
    const float il = 1.0f / (ml0.y * a0 + ml1.y * a1);
    const float e0 = a0 * il, e1 = a1 * il;

    const float* O0 = g_po + (size_t)(z*2  ) * NL * DIMM + (size_t)arow * DIMM + ak0;
    const float* O1 = g_po + (size_t)(z*2+1) * NL * DIMM + (size_t)arow * DIMM + ak0;
    // B loader: row brow = t>>3 (0..31), col bcol = (t&7)*16 (16 floats)
    const int brow = t >> 3, bcol = (t & 7) * 16;
    const float* Bp = B + (size_t)brow * DIMM + bcol;

    float acc[8][4];
    #pragma unroll
    for (int j = 0; j < 8; j++)
        #pragma unroll
        for (int i = 0; i < 4; i++) acc[j][i] = 0.f;

    float4 o0[2], o1[2], br[4];
    #pragma unroll
    for (int i = 0; i < 2; i++) {
        o0[i] = *(const float4*)(O0 + 4*i);
        o1[i] = *(const float4*)(O1 + 4*i);
    }
    #pragma unroll
    for (int i = 0; i < 4; i++) br[i] = *(const float4*)(Bp + 4*i);

    const int nk = DIMM / 32;   // 4
    for (int c = 0; c < nk; c++) {
        #pragma unroll
        for (int i = 0; i < 2; i++) {
            const int kc = ak0 + 4*i;
            As[kc+0][arow] = cf(e0*o0[i].x + e1*o1[i].x);
            As[kc+1][arow] = cf(e0*o0[i].y + e1*o1[i].y);
            As[kc+2][arow] = cf(e0*o0[i].z + e1*o1[i].z);
            As[kc+3][arow] = cf(e0*o0[i].w + e1*o1[i].w);
        }
        #pragma unroll
        for (int i = 0; i < 4; i++) {
            float4 v;
            v.x = cf(br[i].x); v.y = cf(br[i].y);
            v.z = cf(br[i].z); v.w = cf(br[i].w);
            *(float4*)&Bsb[brow][bcol + 4*i] = v;
        }
        __syncthreads();
        if (c + 1 < nk) {
            #pragma unroll
            for (int i = 0; i < 2; i++) {
                o0[i] = *(const float4*)(O0 + (c+1)*32 + 4*i);
                o1[i] = *(const float4*)(O1 + (c+1)*32 + 4*i);
            }
            const float* Bp2 = Bp + (size_t)(c + 1) * 32 * DIMM;
            #pragma unroll
            for (int i = 0; i < 4; i++) br[i] = *(const float4*)(Bp2 + 4*i);
        }
        #pragma unroll
        for (int kk = 0; kk < 32; kk += 8) {
            unsigned a[4], b[8][2];
            a[0] = __float_as_uint(As[kk+qid  ][wm+grp  ]);
            a[1] = __float_as_uint(As[kk+qid  ][wm+grp+8]);
            a[2] = __float_as_uint(As[kk+qid+4][wm+grp  ]);
            a[3] = __float_as_uint(As[kk+qid+4][wm+grp+8]);
            #pragma unroll
            for (int j = 0; j < 8; j++) {
                b[j][0] = __float_as_uint(Bsb[kk+qid  ][wn+8*j+grp]);
                b[j][1] = __float_as_uint(Bsb[kk+qid+4][wn+8*j+grp]);
            }
            #pragma unroll
            for (int j = 0; j < 8; j++) mma8(acc[j], a, b[j]);
        }
        __syncthreads();
    }
    #pragma unroll
    for (int j = 0; j < 8; j++) {
        const int col = wn + 8*j + 2*qid;
        *(float2*)&C[(size_t)(wm+grp  ) * DIMM + col] = make_float2(acc[j][0], acc[j][1]);
        *(float2*)&C[(size_t)(wm+grp+8) * DIMM + col] = make_float2(acc[j][2], acc[j][3]);
    }
}

// reduce 8 per-head partials -> out
__global__ void k_final_red(float* __restrict__ out)
{
    const int i = blockIdx.x * 256 + threadIdx.x;   // float4 index, 32768 total
    const int bt = i >> 11, inner = i & 2047;
    const float4* fp = (const float4*)g_fp;
    float4 r = make_float4(0.f, 0.f, 0.f, 0.f);
    #pragma unroll
    for (int h = 0; h < 8; h++) {
        float4 a = fp[((size_t)bt * 8 + h) * 2048 + inner];
        r.x += a.x; r.y += a.y; r.z += a.z; r.w += a.w;
    }
    ((float4*)out)[i] = r;
}

// ---------------------------------------------------------------------------

extern "C" void kernel_launch(void* const* d_in, const int* in_sizes, int n_in,
                              void* d_out, int out_size)
{
    const float* tensor  = (const float*)d_in[0];
    const float* latents = (const float*)d_in[1];
    const float* Wq      = (const float*)d_in[2];
    const float* Wkv     = (const float*)d_in[3];
    const float* Wo      = (const float*)d_in[4];
    float*       out     = (float*)d_out;

    (void)in_sizes; (void)n_in; (void)out_size;

    cudaFuncSetAttribute(k_flash, cudaFuncAttributeMaxDynamicSharedMemorySize, FLASH_SMEM);

    k_prep_part <<<256, 256>>>(Wq, Wkv, Wo);
    k_prep_red  <<<256, 256>>>();
    k_flash     <<<2 * BTT * HEADS, 256, FLASH_SMEM>>>(tensor, latents);
    k_final_part<<<dim3(HEADS, BTT), 256>>>();
    k_final_red <<<(BTT * NL * DIMM / 4) / 256, 256>>>(out);
}